// round 1
// baseline (speedup 1.0000x reference)
#include <cuda_runtime.h>
#include <math.h>

// Problem dims (fixed by the reference)
#define BB 4
#define SS 2048
#define MD 1024
#define HD 1024

#define BM 128
#define BN 128
#define BK 16
#define TM 8
#define TN 8
#define PADF 4

// Scratch (allocation-free rule: __device__ globals)
__device__ float g_QH[(size_t)BB * SS * HD];
__device__ float g_KH[(size_t)BB * SS * HD];
__device__ float g_VH[(size_t)BB * SS * HD];
__device__ float g_SC[(size_t)BB * SS * SS];

// ---------------------------------------------------------------------------
// NT GEMM: C[m,n] = alpha * sum_k A[m,k]*B[n,k] (+ bias[n])
// Both operands are K-contiguous (row-major with K as inner dim).
// Used for the 3 projections (BIAS=true) and for scores (CAUSAL=true).
// ---------------------------------------------------------------------------
template <bool BIAS, bool CAUSAL>
__global__ void __launch_bounds__(256)
gemm_nt(const float* __restrict__ A, const float* __restrict__ B,
        const float* __restrict__ bias, float* __restrict__ C,
        int K, int ldc, float alpha,
        size_t sA, size_t sB, size_t sC)
{
    const int bm = blockIdx.y, bn = blockIdx.x, bz = blockIdx.z;
    if (CAUSAL && bn * BN > bm * BM + (BM - 1)) return;  // fully above diagonal

    A += (size_t)bz * sA + (size_t)(bm * BM) * K;
    B += (size_t)bz * sB + (size_t)(bn * BN) * K;
    C += (size_t)bz * sC;

    __shared__ __align__(16) float As[BK][BM + PADF];
    __shared__ __align__(16) float Bs[BK][BN + PADF];

    const int tid  = threadIdx.x;
    const int tx   = tid & 15;
    const int ty   = tid >> 4;
    const int lrow = tid >> 2;          // 0..63
    const int lk   = (tid & 3) << 2;    // 0,4,8,12

    const float* Ap0 = A + (size_t)lrow * K + lk;
    const float* Ap1 = Ap0 + (size_t)64 * K;
    const float* Bp0 = B + (size_t)lrow * K + lk;
    const float* Bp1 = Bp0 + (size_t)64 * K;

    float acc[TM][TN];
#pragma unroll
    for (int i = 0; i < TM; i++)
#pragma unroll
        for (int j = 0; j < TN; j++) acc[i][j] = 0.f;

    float4 ra0, ra1, rb0, rb1;
    // prologue: load k-tile 0 into registers
    ra0 = *(const float4*)(Ap0);
    ra1 = *(const float4*)(Ap1);
    rb0 = *(const float4*)(Bp0);
    rb1 = *(const float4*)(Bp1);

    const int nkt = K / BK;
    for (int kt = 0; kt < nkt; ++kt) {
        // regs -> smem (transposed: smem is [k][row])
        As[lk + 0][lrow]      = ra0.x; As[lk + 1][lrow]      = ra0.y;
        As[lk + 2][lrow]      = ra0.z; As[lk + 3][lrow]      = ra0.w;
        As[lk + 0][lrow + 64] = ra1.x; As[lk + 1][lrow + 64] = ra1.y;
        As[lk + 2][lrow + 64] = ra1.z; As[lk + 3][lrow + 64] = ra1.w;
        Bs[lk + 0][lrow]      = rb0.x; Bs[lk + 1][lrow]      = rb0.y;
        Bs[lk + 2][lrow]      = rb0.z; Bs[lk + 3][lrow]      = rb0.w;
        Bs[lk + 0][lrow + 64] = rb1.x; Bs[lk + 1][lrow + 64] = rb1.y;
        Bs[lk + 2][lrow + 64] = rb1.z; Bs[lk + 3][lrow + 64] = rb1.w;
        __syncthreads();

        if (kt + 1 < nkt) {  // prefetch next k-tile (hidden under compute)
            const int off = (kt + 1) * BK;
            ra0 = *(const float4*)(Ap0 + off);
            ra1 = *(const float4*)(Ap1 + off);
            rb0 = *(const float4*)(Bp0 + off);
            rb1 = *(const float4*)(Bp1 + off);
        }

#pragma unroll
        for (int kk = 0; kk < BK; ++kk) {
            float a[TM], b[TN];
            *(float4*)&a[0] = *(const float4*)&As[kk][ty * TM];
            *(float4*)&a[4] = *(const float4*)&As[kk][ty * TM + 4];
            *(float4*)&b[0] = *(const float4*)&Bs[kk][tx * TN];
            *(float4*)&b[4] = *(const float4*)&Bs[kk][tx * TN + 4];
#pragma unroll
            for (int i = 0; i < TM; i++)
#pragma unroll
                for (int j = 0; j < TN; j++)
                    acc[i][j] = fmaf(a[i], b[j], acc[i][j]);
        }
        __syncthreads();
    }

    const int crow = bm * BM + ty * TM;
    const int ccol = bn * BN + tx * TN;
    float bb[TN];
    if (BIAS) {
#pragma unroll
        for (int j = 0; j < TN; j++) bb[j] = bias[ccol + j];
    }
#pragma unroll
    for (int i = 0; i < TM; i++) {
        float4 o0, o1;
        o0.x = acc[i][0] * alpha; o0.y = acc[i][1] * alpha;
        o0.z = acc[i][2] * alpha; o0.w = acc[i][3] * alpha;
        o1.x = acc[i][4] * alpha; o1.y = acc[i][5] * alpha;
        o1.z = acc[i][6] * alpha; o1.w = acc[i][7] * alpha;
        if (BIAS) {
            o0.x += bb[0]; o0.y += bb[1]; o0.z += bb[2]; o0.w += bb[3];
            o1.x += bb[4]; o1.y += bb[5]; o1.z += bb[6]; o1.w += bb[7];
        }
        *(float4*)&C[(size_t)(crow + i) * ldc + ccol]     = o0;
        *(float4*)&C[(size_t)(crow + i) * ldc + ccol + 4] = o1;
    }
}

// ---------------------------------------------------------------------------
// Masked causal softmax over one score row. Also zero-fills entries
// (i, end-of-diagonal-tile] so the NN GEMM can walk whole k-tiles.
// ---------------------------------------------------------------------------
__global__ void __launch_bounds__(256)
softmax_rows(const int* __restrict__ mask, float* __restrict__ SC)
{
    const int b = blockIdx.y;
    const int i = blockIdx.x;
    float* row = SC + ((size_t)b * SS + i) * SS;
    const int* mrow = mask + (size_t)b * SS;
    const int tid = threadIdx.x;
    const int nvalid = i + 1;
    const int nfill = ((i >> 7) + 1) << 7;  // end of this row's diagonal tile

    float vals[8];
    float vmax = -INFINITY;
#pragma unroll
    for (int t = 0; t < 8; ++t) {
        int j = tid + t * 256;
        float s = -INFINITY;
        if (j < nvalid) {
            s = row[j];
            if (mrow[j] == 0) s = -1e9f;
        }
        vals[t] = s;
        vmax = fmaxf(vmax, s);
    }

    __shared__ float red[8];
#pragma unroll
    for (int o = 16; o; o >>= 1) vmax = fmaxf(vmax, __shfl_xor_sync(~0u, vmax, o));
    if ((tid & 31) == 0) red[tid >> 5] = vmax;
    __syncthreads();
    if (tid < 32) {
        float x = (tid < 8) ? red[tid] : -INFINITY;
#pragma unroll
        for (int o = 4; o; o >>= 1) x = fmaxf(x, __shfl_xor_sync(~0u, x, o));
        if (tid == 0) red[0] = x;
    }
    __syncthreads();
    vmax = red[0];
    __syncthreads();

    float lsum = 0.f;
#pragma unroll
    for (int t = 0; t < 8; ++t) {
        float e = __expf(vals[t] - vmax);  // expf(-inf - finite) -> 0
        vals[t] = e;
        lsum += e;
    }
#pragma unroll
    for (int o = 16; o; o >>= 1) lsum += __shfl_xor_sync(~0u, lsum, o);
    if ((tid & 31) == 0) red[tid >> 5] = lsum;
    __syncthreads();
    if (tid < 32) {
        float x = (tid < 8) ? red[tid] : 0.f;
#pragma unroll
        for (int o = 4; o; o >>= 1) x += __shfl_xor_sync(~0u, x, o);
        if (tid == 0) red[0] = x;
    }
    __syncthreads();
    const float rinv = 1.0f / red[0];

#pragma unroll
    for (int t = 0; t < 8; ++t) {
        int j = tid + t * 256;
        if (j < nfill) row[j] = vals[t] * rinv;  // zeros past i
    }
}

// ---------------------------------------------------------------------------
// NN GEMM for OUT = P @ VH, k-range limited by causality (P is zero past the
// diagonal tile, and those tiles are never read).
// ---------------------------------------------------------------------------
__global__ void __launch_bounds__(256)
gemm_nn_causal(const float* __restrict__ A, const float* __restrict__ B,
               float* __restrict__ C, int lda, int ldb, int ldc,
               size_t sA, size_t sB, size_t sC)
{
    const int bm = blockIdx.y, bn = blockIdx.x, bz = blockIdx.z;
    A += (size_t)bz * sA + (size_t)(bm * BM) * lda;
    B += (size_t)bz * sB + bn * BN;
    C += (size_t)bz * sC;

    __shared__ __align__(16) float As[BK][BM + PADF];
    __shared__ __align__(16) float Bs[BK][BN + PADF];

    const int tid  = threadIdx.x;
    const int tx   = tid & 15;
    const int ty   = tid >> 4;
    const int lrow = tid >> 2;          // A-tile: 0..63
    const int lk   = (tid & 3) << 2;
    const int bkr  = tid >> 5;          // B-tile k-row: 0..7
    const int bc4  = (tid & 31) << 2;   // B-tile col: 0..124

    const float* Ap0 = A + (size_t)lrow * lda + lk;
    const float* Ap1 = Ap0 + (size_t)64 * lda;
    const float* Bp0 = B + (size_t)bkr * ldb + bc4;
    const float* Bp1 = Bp0 + (size_t)8 * ldb;

    float acc[TM][TN];
#pragma unroll
    for (int i = 0; i < TM; i++)
#pragma unroll
        for (int j = 0; j < TN; j++) acc[i][j] = 0.f;

    float4 ra0, ra1, rb0, rb1;
    ra0 = *(const float4*)(Ap0);
    ra1 = *(const float4*)(Ap1);
    rb0 = *(const float4*)(Bp0);
    rb1 = *(const float4*)(Bp1);

    const int nkt = (bm + 1) * (BM / BK);  // causal: k <= end of row tile
    for (int kt = 0; kt < nkt; ++kt) {
        As[lk + 0][lrow]      = ra0.x; As[lk + 1][lrow]      = ra0.y;
        As[lk + 2][lrow]      = ra0.z; As[lk + 3][lrow]      = ra0.w;
        As[lk + 0][lrow + 64] = ra1.x; As[lk + 1][lrow + 64] = ra1.y;
        As[lk + 2][lrow + 64] = ra1.z; As[lk + 3][lrow + 64] = ra1.w;
        *(float4*)&Bs[bkr][bc4]     = rb0;
        *(float4*)&Bs[bkr + 8][bc4] = rb1;
        __syncthreads();

        if (kt + 1 < nkt) {
            const int off = (kt + 1) * BK;
            ra0 = *(const float4*)(Ap0 + off);
            ra1 = *(const float4*)(Ap1 + off);
            rb0 = *(const float4*)(Bp0 + (size_t)off * ldb);
            rb1 = *(const float4*)(Bp1 + (size_t)off * ldb);
        }

#pragma unroll
        for (int kk = 0; kk < BK; ++kk) {
            float a[TM], b[TN];
            *(float4*)&a[0] = *(const float4*)&As[kk][ty * TM];
            *(float4*)&a[4] = *(const float4*)&As[kk][ty * TM + 4];
            *(float4*)&b[0] = *(const float4*)&Bs[kk][tx * TN];
            *(float4*)&b[4] = *(const float4*)&Bs[kk][tx * TN + 4];
#pragma unroll
            for (int i = 0; i < TM; i++)
#pragma unroll
                for (int j = 0; j < TN; j++)
                    acc[i][j] = fmaf(a[i], b[j], acc[i][j]);
        }
        __syncthreads();
    }

    const int crow = bm * BM + ty * TM;
    const int ccol = bn * BN + tx * TN;
#pragma unroll
    for (int i = 0; i < TM; i++) {
        float4 o0, o1;
        o0.x = acc[i][0]; o0.y = acc[i][1]; o0.z = acc[i][2]; o0.w = acc[i][3];
        o1.x = acc[i][4]; o1.y = acc[i][5]; o1.z = acc[i][6]; o1.w = acc[i][7];
        *(float4*)&C[(size_t)(crow + i) * ldc + ccol]     = o0;
        *(float4*)&C[(size_t)(crow + i) * ldc + ccol + 4] = o1;
    }
}

// ---------------------------------------------------------------------------
extern "C" void kernel_launch(void* const* d_in, const int* in_sizes, int n_in,
                              void* d_out, int out_size)
{
    (void)in_sizes; (void)n_in; (void)out_size;

    const float* q    = (const float*)d_in[0];
    const float* k    = (const float*)d_in[1];
    const float* v    = (const float*)d_in[2];
    const int*   mask = (const int*)  d_in[3];
    const float* Wq   = (const float*)d_in[4];
    const float* bq   = (const float*)d_in[5];
    const float* Wk   = (const float*)d_in[6];
    const float* bk   = (const float*)d_in[7];
    const float* Wv   = (const float*)d_in[8];
    const float* bv   = (const float*)d_in[9];
    float* out = (float*)d_out;

    static float* QH = nullptr;
    static float* KH = nullptr;
    static float* VH = nullptr;
    static float* SC = nullptr;
    if (!QH) {
        void* p;
        cudaGetSymbolAddress(&p, g_QH); QH = (float*)p;
        cudaGetSymbolAddress(&p, g_KH); KH = (float*)p;
        cudaGetSymbolAddress(&p, g_VH); VH = (float*)p;
        cudaGetSymbolAddress(&p, g_SC); SC = (float*)p;
    }

    const float inv_sqrt_h = 1.0f / 32.0f;  // 1/sqrt(1024)

    // 1) Projections: [B*S, M] @ W^T + b  -> [B*S, H]
    dim3 gproj(HD / BN, (BB * SS) / BM, 1);
    gemm_nt<true, false><<<gproj, 256>>>(q, Wq, bq, QH, MD, HD, 1.0f, 0, 0, 0);
    gemm_nt<true, false><<<gproj, 256>>>(k, Wk, bk, KH, MD, HD, 1.0f, 0, 0, 0);
    gemm_nt<true, false><<<gproj, 256>>>(v, Wv, bv, VH, MD, HD, 1.0f, 0, 0, 0);

    // 2) Scores: per batch, QH @ KH^T / 32 (upper-triangle tiles skipped)
    dim3 gsc(SS / BN, SS / BM, BB);
    gemm_nt<false, true><<<gsc, 256>>>(QH, KH, nullptr, SC, HD, SS, inv_sqrt_h,
                                       (size_t)SS * HD, (size_t)SS * HD,
                                       (size_t)SS * SS);

    // 3) Masked causal softmax, one block per row
    dim3 gsm(SS, BB);
    softmax_rows<<<gsm, 256>>>(mask, SC);

    // 4) OUT = P @ VH (k-tiles limited by causality)
    dim3 go(HD / BN, SS / BM, BB);
    gemm_nn_causal<<<go, 256>>>(SC, VH, out, SS, HD, HD,
                                (size_t)SS * SS, (size_t)SS * HD,
                                (size_t)SS * HD);
}

// round 3
// speedup vs baseline: 2.2000x; 2.2000x over previous
#include <cuda_runtime.h>
#include <cuda_bf16.h>
#include <mma.h>
#include <math.h>
#include <stdint.h>

using namespace nvcuda;

// Problem dims (fixed)
#define BB 4
#define SS 2048
#define MD 1024
#define HD 1024
#define NT 8192   // BB*SS

#define KC 32          // K elements per chunk
#define KPAD 48        // padded K-major smem row (elements)
#define NPAD 144       // padded N-major smem row (elements, NN B tile)

// Stage layouts (bytes)
#define TILE_KMAJ (128 * KPAD * 2)   // 12288
#define TILE_NMAJ (KC * NPAD * 2)    // 9216
#define STAGE_NT  (4 * TILE_KMAJ)                // 49152
#define STAGE_NN  (2 * TILE_KMAJ + 2 * TILE_NMAJ) // 43008
#define SMEMSZ    (2 * STAGE_NT)                 // 98304

// ---------------------------------------------------------------------------
// Scratch (__device__ globals; allocation-free rule)
// ---------------------------------------------------------------------------
__device__ __align__(256) __nv_bfloat16 g_Xq_hi[(size_t)NT * MD];
__device__ __align__(256) __nv_bfloat16 g_Xq_lo[(size_t)NT * MD];
__device__ __align__(256) __nv_bfloat16 g_Xk_hi[(size_t)NT * MD];
__device__ __align__(256) __nv_bfloat16 g_Xk_lo[(size_t)NT * MD];
__device__ __align__(256) __nv_bfloat16 g_Xv_hi[(size_t)NT * MD];
__device__ __align__(256) __nv_bfloat16 g_Xv_lo[(size_t)NT * MD];
__device__ __align__(256) __nv_bfloat16 g_Wq_hi[(size_t)HD * MD];
__device__ __align__(256) __nv_bfloat16 g_Wq_lo[(size_t)HD * MD];
__device__ __align__(256) __nv_bfloat16 g_Wk_hi[(size_t)HD * MD];
__device__ __align__(256) __nv_bfloat16 g_Wk_lo[(size_t)HD * MD];
__device__ __align__(256) __nv_bfloat16 g_Wv_hi[(size_t)HD * MD];
__device__ __align__(256) __nv_bfloat16 g_Wv_lo[(size_t)HD * MD];
__device__ __align__(256) __nv_bfloat16 g_QH_hi[(size_t)NT * HD];
__device__ __align__(256) __nv_bfloat16 g_QH_lo[(size_t)NT * HD];
__device__ __align__(256) __nv_bfloat16 g_KH_hi[(size_t)NT * HD];
__device__ __align__(256) __nv_bfloat16 g_KH_lo[(size_t)NT * HD];
__device__ __align__(256) __nv_bfloat16 g_VH_hi[(size_t)NT * HD];
__device__ __align__(256) __nv_bfloat16 g_VH_lo[(size_t)NT * HD];
__device__ __align__(256) float         g_SC[(size_t)BB * SS * SS];
__device__ __align__(256) __nv_bfloat16 g_P_hi[(size_t)BB * SS * SS];
__device__ __align__(256) __nv_bfloat16 g_P_lo[(size_t)BB * SS * SS];

// ---------------------------------------------------------------------------
__device__ __forceinline__ uint32_t smem_u32(const void* p) {
    uint32_t a;
    asm("{ .reg .u64 t; cvta.to.shared.u64 t, %1; cvt.u32.u64 %0, t; }"
        : "=r"(a) : "l"(p));
    return a;
}
#define CP16(dst, src) asm volatile("cp.async.cg.shared.global [%0], [%1], 16;" :: "r"(dst), "l"(src))
#define CP_COMMIT()    asm volatile("cp.async.commit_group;" ::: "memory")
#define CP_WAIT1()     asm volatile("cp.async.wait_group 1;" ::: "memory")
#define CP_WAIT0()     asm volatile("cp.async.wait_group 0;" ::: "memory")

__device__ __forceinline__ void split_bf16(float x, __nv_bfloat16& h, __nv_bfloat16& l) {
    h = __float2bfloat16(x);
    l = __float2bfloat16(x - __bfloat162float(h));
}

// ---------------------------------------------------------------------------
// 3xBF16 wmma GEMM, 128x128 CTA tile, 8 warps (4x2), warp tile 32x64.
// MODE 0: NT, C = A*B^T + bias -> bf16 hi/lo (projections)
// MODE 2: NT, C = alpha*(A*B^T) -> fp32, causal tile skip (scores)
// MODE 3: NN, C = A*B -> fp32, k-limited by causality (PV)
// A is [M,K] hi/lo bf16 row-major. B: MODE 0/2 -> [N,K] row-major (NT);
// MODE 3 -> [K,N] row-major (NN).
// ---------------------------------------------------------------------------
template <int MODE>
__global__ void __launch_bounds__(256)
gemm3w(const __nv_bfloat16* __restrict__ Ahi, const __nv_bfloat16* __restrict__ Alo,
       const __nv_bfloat16* __restrict__ Bhi, const __nv_bfloat16* __restrict__ Blo,
       const float* __restrict__ bias,
       __nv_bfloat16* __restrict__ Chi, __nv_bfloat16* __restrict__ Clo,
       float* __restrict__ Cf,
       int K, int ldb, int ldc, float alpha, size_t sA, size_t sB, size_t sC)
{
    constexpr bool IS_NN = (MODE == 3);
    constexpr int STAGE = IS_NN ? STAGE_NN : STAGE_NT;
    constexpr int OFF_AH = 0;
    constexpr int OFF_AL = TILE_KMAJ;
    constexpr int OFF_BH = 2 * TILE_KMAJ;
    constexpr int OFF_BL = IS_NN ? (2 * TILE_KMAJ + TILE_NMAJ) : (3 * TILE_KMAJ);

    const int bm = blockIdx.y, bn = blockIdx.x, bz = blockIdx.z;
    if (MODE == 2 && bn > bm) return;

    extern __shared__ char smem[];
    const uint32_t sb = smem_u32(smem);
    const int tid = threadIdx.x;

    const char* gAh = (const char*)(Ahi + (size_t)bz * sA) + (size_t)(bm * 128) * (K * 2);
    const char* gAl = (const char*)(Alo + (size_t)bz * sA) + (size_t)(bm * 128) * (K * 2);
    const char* gBh;
    const char* gBl;
    if (IS_NN) {
        gBh = (const char*)(Bhi + (size_t)bz * sB) + (size_t)bn * 256;
        gBl = (const char*)(Blo + (size_t)bz * sB) + (size_t)bn * 256;
    } else {
        gBh = (const char*)(Bhi + (size_t)bz * sB) + (size_t)(bn * 128) * (K * 2);
        gBl = (const char*)(Blo + (size_t)bz * sB) + (size_t)(bn * 128) * (K * 2);
    }
    const size_t ldb2 = (size_t)ldb * 2;

    const int nkt = (MODE == 3) ? (bm + 1) * 4 : (K / KC);

    // ---- chunk loader (cp.async) ----
    auto load_chunk = [&](int c, int buf) {
        const uint32_t st = sb + buf * STAGE;
#pragma unroll
        for (int it = 0; it < 2; ++it) {
            const int idx = tid + it * 256;
            // A tiles: 128 rows x 64B (4 x 16B segs)
            {
                const int row = idx >> 2, seg = idx & 3;
                const size_t go = (size_t)row * (K * 2) + (size_t)c * 64 + seg * 16;
                const uint32_t so = row * (KPAD * 2) + seg * 16;
                CP16(st + OFF_AH + so, gAh + go);
                CP16(st + OFF_AL + so, gAl + go);
            }
            if (!IS_NN) {
                const int row = idx >> 2, seg = idx & 3;
                const size_t go = (size_t)row * (K * 2) + (size_t)c * 64 + seg * 16;
                const uint32_t so = row * (KPAD * 2) + seg * 16;
                CP16(st + OFF_BH + so, gBh + go);
                CP16(st + OFF_BL + so, gBl + go);
            } else {
                // B tile: 32 rows x 256B (16 x 16B segs)
                const int row = idx >> 4, seg = idx & 15;
                const size_t go = ((size_t)c * KC + row) * ldb2 + seg * 16;
                const uint32_t so = row * (NPAD * 2) + seg * 16;
                CP16(st + OFF_BH + so, gBh + go);
                CP16(st + OFF_BL + so, gBl + go);
            }
        }
        CP_COMMIT();
    };

    // ---- wmma setup ----
    const int wid = tid >> 5;
    const int wm = wid & 3;        // 0..3 -> m offset
    const int wn = wid >> 2;       // 0..1 -> n offset
    const int m_base = wm * 32;
    const int n_base = wn * 64;

    wmma::fragment<wmma::accumulator, 16, 16, 16, float> acc[2][4];
#pragma unroll
    for (int i = 0; i < 2; ++i)
#pragma unroll
        for (int j = 0; j < 4; ++j) wmma::fill_fragment(acc[i][j], 0.0f);

    load_chunk(0, 0);

    for (int c = 0; c < nkt; ++c) {
        const int buf = c & 1;
        if (c + 1 < nkt) { load_chunk(c + 1, buf ^ 1); CP_WAIT1(); }
        else             { CP_WAIT0(); }
        __syncthreads();

        const __nv_bfloat16* As_h = (const __nv_bfloat16*)(smem + buf * STAGE + OFF_AH);
        const __nv_bfloat16* As_l = (const __nv_bfloat16*)(smem + buf * STAGE + OFF_AL);
        const __nv_bfloat16* Bs_h = (const __nv_bfloat16*)(smem + buf * STAGE + OFF_BH);
        const __nv_bfloat16* Bs_l = (const __nv_bfloat16*)(smem + buf * STAGE + OFF_BL);

#pragma unroll
        for (int ks = 0; ks < KC; ks += 16) {
            wmma::fragment<wmma::matrix_a, 16, 16, 16, __nv_bfloat16, wmma::row_major> ah[2], al[2];
#pragma unroll
            for (int mi = 0; mi < 2; ++mi) {
                wmma::load_matrix_sync(ah[mi], As_h + (m_base + mi * 16) * KPAD + ks, KPAD);
                wmma::load_matrix_sync(al[mi], As_l + (m_base + mi * 16) * KPAD + ks, KPAD);
            }
            if (!IS_NN) {
                wmma::fragment<wmma::matrix_b, 16, 16, 16, __nv_bfloat16, wmma::col_major> bh[4], bl[4];
#pragma unroll
                for (int ni = 0; ni < 4; ++ni) {
                    wmma::load_matrix_sync(bh[ni], Bs_h + (n_base + ni * 16) * KPAD + ks, KPAD);
                    wmma::load_matrix_sync(bl[ni], Bs_l + (n_base + ni * 16) * KPAD + ks, KPAD);
                }
#pragma unroll
                for (int ni = 0; ni < 4; ++ni)
#pragma unroll
                    for (int mi = 0; mi < 2; ++mi)
                        wmma::mma_sync(acc[mi][ni], ah[mi], bh[ni], acc[mi][ni]);
#pragma unroll
                for (int ni = 0; ni < 4; ++ni)
#pragma unroll
                    for (int mi = 0; mi < 2; ++mi)
                        wmma::mma_sync(acc[mi][ni], al[mi], bh[ni], acc[mi][ni]);
#pragma unroll
                for (int ni = 0; ni < 4; ++ni)
#pragma unroll
                    for (int mi = 0; mi < 2; ++mi)
                        wmma::mma_sync(acc[mi][ni], ah[mi], bl[ni], acc[mi][ni]);
            } else {
                wmma::fragment<wmma::matrix_b, 16, 16, 16, __nv_bfloat16, wmma::row_major> bh[4], bl[4];
#pragma unroll
                for (int ni = 0; ni < 4; ++ni) {
                    wmma::load_matrix_sync(bh[ni], Bs_h + ks * NPAD + (n_base + ni * 16), NPAD);
                    wmma::load_matrix_sync(bl[ni], Bs_l + ks * NPAD + (n_base + ni * 16), NPAD);
                }
#pragma unroll
                for (int ni = 0; ni < 4; ++ni)
#pragma unroll
                    for (int mi = 0; mi < 2; ++mi)
                        wmma::mma_sync(acc[mi][ni], ah[mi], bh[ni], acc[mi][ni]);
#pragma unroll
                for (int ni = 0; ni < 4; ++ni)
#pragma unroll
                    for (int mi = 0; mi < 2; ++mi)
                        wmma::mma_sync(acc[mi][ni], al[mi], bh[ni], acc[mi][ni]);
#pragma unroll
                for (int ni = 0; ni < 4; ++ni)
#pragma unroll
                    for (int mi = 0; mi < 2; ++mi)
                        wmma::mma_sync(acc[mi][ni], ah[mi], bl[ni], acc[mi][ni]);
            }
        }
        __syncthreads();
    }

    // ---- epilogue ----
    if (MODE == 0) {
        // stage fp32 tile in smem, then bias + hi/lo split
        float* fs = (float*)smem;
#pragma unroll
        for (int mi = 0; mi < 2; ++mi)
#pragma unroll
            for (int ni = 0; ni < 4; ++ni)
                wmma::store_matrix_sync(fs + (m_base + mi * 16) * 128 + n_base + ni * 16,
                                        acc[mi][ni], 128, wmma::mem_row_major);
        __syncthreads();
        const int row = tid >> 1;
        const int col0 = (tid & 1) * 64;
        const int gcol0 = bn * 128 + col0;
        const size_t gbase = (size_t)(bm * 128 + row) * ldc + gcol0;
#pragma unroll
        for (int j = 0; j < 64; j += 8) {
            union { __nv_bfloat16 h[8]; uint4 v; } uh, ul;
#pragma unroll
            for (int t = 0; t < 8; ++t) {
                float x = fs[row * 128 + col0 + j + t] + bias[gcol0 + j + t];
                split_bf16(x, uh.h[t], ul.h[t]);
            }
            *(uint4*)(Chi + gbase + j) = uh.v;
            *(uint4*)(Clo + gbase + j) = ul.v;
        }
    } else {
        float* cp;
        if (MODE == 2) {
            cp = Cf + (size_t)bz * sC;
#pragma unroll
            for (int mi = 0; mi < 2; ++mi)
#pragma unroll
                for (int ni = 0; ni < 4; ++ni) {
#pragma unroll
                    for (int t = 0; t < acc[mi][ni].num_elements; ++t)
                        acc[mi][ni].x[t] *= alpha;
                }
        } else {
            cp = Cf + (size_t)bz * sC;
        }
#pragma unroll
        for (int mi = 0; mi < 2; ++mi)
#pragma unroll
            for (int ni = 0; ni < 4; ++ni)
                wmma::store_matrix_sync(cp + (size_t)(bm * 128 + m_base + mi * 16) * ldc
                                           + bn * 128 + n_base + ni * 16,
                                        acc[mi][ni], ldc, wmma::mem_row_major);
    }
}

// ---------------------------------------------------------------------------
// Elementwise fp32 -> bf16 hi/lo split
// ---------------------------------------------------------------------------
__global__ void __launch_bounds__(256)
convert_split(const float* __restrict__ src, __nv_bfloat16* __restrict__ hi,
              __nv_bfloat16* __restrict__ lo, size_t n4)
{
    size_t i = (size_t)blockIdx.x * blockDim.x + threadIdx.x;
    if (i >= n4) return;
    float4 x = ((const float4*)src)[i];
    union { __nv_bfloat16 h[4]; uint2 u; } H, L;
    split_bf16(x.x, H.h[0], L.h[0]);
    split_bf16(x.y, H.h[1], L.h[1]);
    split_bf16(x.z, H.h[2], L.h[2]);
    split_bf16(x.w, H.h[3], L.h[3]);
    ((uint2*)hi)[i] = H.u;
    ((uint2*)lo)[i] = L.u;
}

// ---------------------------------------------------------------------------
// Masked causal softmax. Reads SC fp32; writes P hi/lo bf16, zero-filled to
// the 128-tile boundary so PV can walk whole k-chunks.
// ---------------------------------------------------------------------------
__global__ void __launch_bounds__(256)
softmax_rows(const int* __restrict__ mask, const float* __restrict__ SC,
             __nv_bfloat16* __restrict__ Phi, __nv_bfloat16* __restrict__ Plo)
{
    const int b = blockIdx.y;
    const int i = blockIdx.x;
    const size_t rowoff = ((size_t)b * SS + i) * SS;
    const float* row = SC + rowoff;
    const int* mrow = mask + (size_t)b * SS;
    const int tid = threadIdx.x;
    const int nvalid = i + 1;
    const int nfill = ((i >> 7) + 1) << 7;

    float vals[8];
    float vmax = -INFINITY;
#pragma unroll
    for (int t = 0; t < 8; ++t) {
        int j = tid + t * 256;
        float s = -INFINITY;
        if (j < nvalid) {
            s = row[j];
            if (mrow[j] == 0) s = -1e9f;
        }
        vals[t] = s;
        vmax = fmaxf(vmax, s);
    }

    __shared__ float red[8];
#pragma unroll
    for (int o = 16; o; o >>= 1) vmax = fmaxf(vmax, __shfl_xor_sync(~0u, vmax, o));
    if ((tid & 31) == 0) red[tid >> 5] = vmax;
    __syncthreads();
    if (tid < 32) {
        float x = (tid < 8) ? red[tid] : -INFINITY;
#pragma unroll
        for (int o = 4; o; o >>= 1) x = fmaxf(x, __shfl_xor_sync(~0u, x, o));
        if (tid == 0) red[0] = x;
    }
    __syncthreads();
    vmax = red[0];
    __syncthreads();

    float lsum = 0.f;
#pragma unroll
    for (int t = 0; t < 8; ++t) {
        float e = __expf(vals[t] - vmax);
        vals[t] = e;
        lsum += e;
    }
#pragma unroll
    for (int o = 16; o; o >>= 1) lsum += __shfl_xor_sync(~0u, lsum, o);
    if ((tid & 31) == 0) red[tid >> 5] = lsum;
    __syncthreads();
    if (tid < 32) {
        float x = (tid < 8) ? red[tid] : 0.f;
#pragma unroll
        for (int o = 4; o; o >>= 1) x += __shfl_xor_sync(~0u, x, o);
        if (tid == 0) red[0] = x;
    }
    __syncthreads();
    const float rinv = 1.0f / red[0];

#pragma unroll
    for (int t = 0; t < 8; ++t) {
        int j = tid + t * 256;
        if (j < nfill) {
            float p = vals[t] * rinv;  // 0 for j > i
            __nv_bfloat16 H, L;
            split_bf16(p, H, L);
            Phi[rowoff + j] = H;
            Plo[rowoff + j] = L;
        }
    }
}

// ---------------------------------------------------------------------------
extern "C" void kernel_launch(void* const* d_in, const int* in_sizes, int n_in,
                              void* d_out, int out_size)
{
    (void)in_sizes; (void)n_in; (void)out_size;

    const float* q    = (const float*)d_in[0];
    const float* k    = (const float*)d_in[1];
    const float* v    = (const float*)d_in[2];
    const int*   mask = (const int*)  d_in[3];
    const float* Wq   = (const float*)d_in[4];
    const float* bq   = (const float*)d_in[5];
    const float* Wk   = (const float*)d_in[6];
    const float* bk   = (const float*)d_in[7];
    const float* Wv   = (const float*)d_in[8];
    const float* bv   = (const float*)d_in[9];
    float* out = (float*)d_out;

    static bool init = false;
    static __nv_bfloat16 *Xqh, *Xql, *Xkh, *Xkl, *Xvh, *Xvl;
    static __nv_bfloat16 *Wqh, *Wql, *Wkh, *Wkl, *Wvh, *Wvl;
    static __nv_bfloat16 *QHh, *QHl, *KHh, *KHl, *VHh, *VHl, *Ph, *Pl;
    static float *SC;
    if (!init) {
        void* p;
        cudaGetSymbolAddress(&p, g_Xq_hi); Xqh = (__nv_bfloat16*)p;
        cudaGetSymbolAddress(&p, g_Xq_lo); Xql = (__nv_bfloat16*)p;
        cudaGetSymbolAddress(&p, g_Xk_hi); Xkh = (__nv_bfloat16*)p;
        cudaGetSymbolAddress(&p, g_Xk_lo); Xkl = (__nv_bfloat16*)p;
        cudaGetSymbolAddress(&p, g_Xv_hi); Xvh = (__nv_bfloat16*)p;
        cudaGetSymbolAddress(&p, g_Xv_lo); Xvl = (__nv_bfloat16*)p;
        cudaGetSymbolAddress(&p, g_Wq_hi); Wqh = (__nv_bfloat16*)p;
        cudaGetSymbolAddress(&p, g_Wq_lo); Wql = (__nv_bfloat16*)p;
        cudaGetSymbolAddress(&p, g_Wk_hi); Wkh = (__nv_bfloat16*)p;
        cudaGetSymbolAddress(&p, g_Wk_lo); Wkl = (__nv_bfloat16*)p;
        cudaGetSymbolAddress(&p, g_Wv_hi); Wvh = (__nv_bfloat16*)p;
        cudaGetSymbolAddress(&p, g_Wv_lo); Wvl = (__nv_bfloat16*)p;
        cudaGetSymbolAddress(&p, g_QH_hi); QHh = (__nv_bfloat16*)p;
        cudaGetSymbolAddress(&p, g_QH_lo); QHl = (__nv_bfloat16*)p;
        cudaGetSymbolAddress(&p, g_KH_hi); KHh = (__nv_bfloat16*)p;
        cudaGetSymbolAddress(&p, g_KH_lo); KHl = (__nv_bfloat16*)p;
        cudaGetSymbolAddress(&p, g_VH_hi); VHh = (__nv_bfloat16*)p;
        cudaGetSymbolAddress(&p, g_VH_lo); VHl = (__nv_bfloat16*)p;
        cudaGetSymbolAddress(&p, g_P_hi);  Ph  = (__nv_bfloat16*)p;
        cudaGetSymbolAddress(&p, g_P_lo);  Pl  = (__nv_bfloat16*)p;
        cudaGetSymbolAddress(&p, g_SC);    SC  = (float*)p;
        cudaFuncSetAttribute((const void*)gemm3w<0>, cudaFuncAttributeMaxDynamicSharedMemorySize, SMEMSZ);
        cudaFuncSetAttribute((const void*)gemm3w<2>, cudaFuncAttributeMaxDynamicSharedMemorySize, SMEMSZ);
        cudaFuncSetAttribute((const void*)gemm3w<3>, cudaFuncAttributeMaxDynamicSharedMemorySize, SMEMSZ);
        init = true;
    }

    // 1) Split inputs to bf16 hi/lo
    const size_t nX4 = (size_t)NT * MD / 4;
    const size_t nW4 = (size_t)HD * MD / 4;
    convert_split<<<(unsigned)((nX4 + 255) / 256), 256>>>(q, Xqh, Xql, nX4);
    convert_split<<<(unsigned)((nX4 + 255) / 256), 256>>>(k, Xkh, Xkl, nX4);
    convert_split<<<(unsigned)((nX4 + 255) / 256), 256>>>(v, Xvh, Xvl, nX4);
    convert_split<<<(unsigned)((nW4 + 255) / 256), 256>>>(Wq, Wqh, Wql, nW4);
    convert_split<<<(unsigned)((nW4 + 255) / 256), 256>>>(Wk, Wkh, Wkl, nW4);
    convert_split<<<(unsigned)((nW4 + 255) / 256), 256>>>(Wv, Wvh, Wvl, nW4);

    // 2) Projections (NT, bias, bf16 hi/lo out)
    dim3 gproj(HD / 128, NT / 128, 1);
    gemm3w<0><<<gproj, 256, SMEMSZ>>>(Xqh, Xql, Wqh, Wql, bq, QHh, QHl, nullptr,
                                      MD, MD, HD, 1.f, 0, 0, 0);
    gemm3w<0><<<gproj, 256, SMEMSZ>>>(Xkh, Xkl, Wkh, Wkl, bk, KHh, KHl, nullptr,
                                      MD, MD, HD, 1.f, 0, 0, 0);
    gemm3w<0><<<gproj, 256, SMEMSZ>>>(Xvh, Xvl, Wvh, Wvl, bv, VHh, VHl, nullptr,
                                      MD, MD, HD, 1.f, 0, 0, 0);

    // 3) Scores (NT, causal skip), alpha = 1/sqrt(1024)
    dim3 gsc(SS / 128, SS / 128, BB);
    gemm3w<2><<<gsc, 256, SMEMSZ>>>(QHh, QHl, KHh, KHl, nullptr, nullptr, nullptr, SC,
                                    HD, HD, SS, 1.0f / 32.0f,
                                    (size_t)SS * HD, (size_t)SS * HD, (size_t)SS * SS);

    // 4) Softmax + bf16 hi/lo split of P
    softmax_rows<<<dim3(SS, BB), 256>>>(mask, SC, Ph, Pl);

    // 5) OUT = P @ VH (NN, k-limited by causality)
    dim3 go(HD / 128, SS / 128, BB);
    gemm3w<3><<<go, 256, SMEMSZ>>>(Ph, Pl, VHh, VHl, nullptr, nullptr, nullptr, out,
                                   SS, HD, HD, 1.f,
                                   (size_t)SS * SS, (size_t)SS * HD, (size_t)SS * HD);
}

// round 4
// speedup vs baseline: 2.4336x; 1.1062x over previous
#include <cuda_runtime.h>
#include <cuda_bf16.h>
#include <math.h>
#include <stdint.h>

// Problem dims (fixed)
#define BB 4
#define SS 2048
#define MD 1024
#define HD 1024
#define NT 8192   // BB*SS

// GEMM tiling: CTA 128x256, 8 warps (2x4) of 64x64, K-chunk 64
#define KC 64
#define OFF_AH 0
#define OFF_AL 16384
#define OFF_BH 32768
#define OFF_BL 65536
#define STAGE  98304
#define SMEMSZ (2 * STAGE)   // 192 KB

#define SWZ(o) ((o) ^ (((o) >> 3) & 0x70))

// ---------------------------------------------------------------------------
// Scratch (__device__ globals; allocation-free rule)
// ---------------------------------------------------------------------------
__device__ __align__(256) __nv_bfloat16 g_Xq_hi[(size_t)NT * MD];
__device__ __align__(256) __nv_bfloat16 g_Xq_lo[(size_t)NT * MD];
__device__ __align__(256) __nv_bfloat16 g_Xk_hi[(size_t)NT * MD];
__device__ __align__(256) __nv_bfloat16 g_Xk_lo[(size_t)NT * MD];
__device__ __align__(256) __nv_bfloat16 g_Xv_hi[(size_t)NT * MD];
__device__ __align__(256) __nv_bfloat16 g_Xv_lo[(size_t)NT * MD];
__device__ __align__(256) __nv_bfloat16 g_Wq_hi[(size_t)HD * MD];
__device__ __align__(256) __nv_bfloat16 g_Wq_lo[(size_t)HD * MD];
__device__ __align__(256) __nv_bfloat16 g_Wk_hi[(size_t)HD * MD];
__device__ __align__(256) __nv_bfloat16 g_Wk_lo[(size_t)HD * MD];
__device__ __align__(256) __nv_bfloat16 g_Wv_hi[(size_t)HD * MD];
__device__ __align__(256) __nv_bfloat16 g_Wv_lo[(size_t)HD * MD];
__device__ __align__(256) __nv_bfloat16 g_QH_hi[(size_t)NT * HD];
__device__ __align__(256) __nv_bfloat16 g_QH_lo[(size_t)NT * HD];
__device__ __align__(256) __nv_bfloat16 g_KH_hi[(size_t)NT * HD];
__device__ __align__(256) __nv_bfloat16 g_KH_lo[(size_t)NT * HD];
__device__ __align__(256) __nv_bfloat16 g_VH_hi[(size_t)NT * HD];
__device__ __align__(256) __nv_bfloat16 g_VH_lo[(size_t)NT * HD];
__device__ __align__(256) __nv_bfloat16 g_VT_hi[(size_t)BB * HD * SS];
__device__ __align__(256) __nv_bfloat16 g_VT_lo[(size_t)BB * HD * SS];
__device__ __align__(256) float         g_SC[(size_t)BB * SS * SS];
__device__ __align__(256) __nv_bfloat16 g_P_hi[(size_t)BB * SS * SS];
__device__ __align__(256) __nv_bfloat16 g_P_lo[(size_t)BB * SS * SS];

// ---------------------------------------------------------------------------
__device__ __forceinline__ uint32_t smem_u32(const void* p) {
    uint32_t a;
    asm("{ .reg .u64 t; cvta.to.shared.u64 t, %1; cvt.u32.u64 %0, t; }"
        : "=r"(a) : "l"(p));
    return a;
}
#define CP16(dst, src) asm volatile("cp.async.cg.shared.global [%0], [%1], 16;" :: "r"(dst), "l"(src))
#define CP_COMMIT()    asm volatile("cp.async.commit_group;" ::: "memory")
#define CP_WAIT1()     asm volatile("cp.async.wait_group 1;" ::: "memory")
#define CP_WAIT0()     asm volatile("cp.async.wait_group 0;" ::: "memory")

__device__ __forceinline__ void ldsm4(uint32_t r[4], uint32_t a) {
    asm volatile("ldmatrix.sync.aligned.m8n8.x4.shared.b16 {%0,%1,%2,%3}, [%4];"
                 : "=r"(r[0]), "=r"(r[1]), "=r"(r[2]), "=r"(r[3]) : "r"(a));
}
__device__ __forceinline__ void mma_bf16(float d[4], const uint32_t a[4],
                                         uint32_t b0, uint32_t b1) {
    asm volatile(
        "mma.sync.aligned.m16n8k16.row.col.f32.bf16.bf16.f32 "
        "{%0,%1,%2,%3}, {%4,%5,%6,%7}, {%8,%9}, {%0,%1,%2,%3};"
        : "+f"(d[0]), "+f"(d[1]), "+f"(d[2]), "+f"(d[3])
        : "r"(a[0]), "r"(a[1]), "r"(a[2]), "r"(a[3]), "r"(b0), "r"(b1));
}

__device__ __forceinline__ void split_bf16(float x, __nv_bfloat16& h, __nv_bfloat16& l) {
    h = __float2bfloat16(x);
    l = __float2bfloat16(x - __bfloat162float(h));
}
__device__ __forceinline__ uint32_t pack_bf2(__nv_bfloat16 a, __nv_bfloat16 b) {
    union { __nv_bfloat162 v; uint32_t u; } t;
    t.v.x = a; t.v.y = b;
    return t.u;
}

// ---------------------------------------------------------------------------
// 3xBF16 mma.sync GEMM (NT): C = alpha*(A*B^T) [+ bias]
// A: [M,K] hi/lo bf16, rows K-contig (lda). B: [N,K] hi/lo bf16 (ldb).
// CTA tile 128x256, 8 warps of 64x64, KC=64, 2-stage cp.async.
// MODE 0: proj -> bf16 hi/lo out + bias
// MODE 2: scores -> fp32 out, alpha, causal tile skip (2*bn <= bm)
// MODE 3: PV -> fp32 out, k-chunks limited to (bm+1)*2
// ---------------------------------------------------------------------------
template <int MODE>
__global__ void __launch_bounds__(256, 1)
gemm3m(const __nv_bfloat16* __restrict__ Ahi, const __nv_bfloat16* __restrict__ Alo,
       const __nv_bfloat16* __restrict__ Bhi, const __nv_bfloat16* __restrict__ Blo,
       const float* __restrict__ bias,
       __nv_bfloat16* __restrict__ Chi, __nv_bfloat16* __restrict__ Clo,
       float* __restrict__ Cf,
       int lda, int ldb, int ldc, int nkt0, float alpha,
       size_t sA, size_t sB, size_t sC)
{
    const int bm = blockIdx.y, bn = blockIdx.x, bz = blockIdx.z;
    if (MODE == 2 && 2 * bn > bm) return;
    const int nkt = (MODE == 3) ? (bm + 1) * 2 : nkt0;

    extern __shared__ char smem[];
    const uint32_t sb = smem_u32(smem);
    const int tid = threadIdx.x, lane = tid & 31, wid = tid >> 5;
    const int wm = wid >> 2, wn = wid & 3;

    const char* gAh = (const char*)(Ahi + (size_t)bz * sA + (size_t)(bm * 128) * lda);
    const char* gAl = (const char*)(Alo + (size_t)bz * sA + (size_t)(bm * 128) * lda);
    const char* gBh = (const char*)(Bhi + (size_t)bz * sB + (size_t)(bn * 256) * ldb);
    const char* gBl = (const char*)(Blo + (size_t)bz * sB + (size_t)(bn * 256) * ldb);
    const size_t ldaB = (size_t)lda * 2, ldbB = (size_t)ldb * 2;

    auto load_chunk = [&](int c, int buf) {
        const uint32_t st = sb + buf * STAGE;
        const size_t cb = (size_t)c * 128;
#pragma unroll
        for (int i = 0; i < 4; ++i) {          // A: 128 rows x 128B
            const int idx = tid + i * 256;
            const int row = idx >> 3, seg = (idx & 7) * 16;
            const size_t go = (size_t)row * ldaB + cb + seg;
            const uint32_t so = SWZ(row * 128 + seg);
            CP16(st + OFF_AH + so, gAh + go);
            CP16(st + OFF_AL + so, gAl + go);
        }
#pragma unroll
        for (int i = 0; i < 8; ++i) {          // B: 256 rows x 128B
            const int idx = tid + i * 256;
            const int row = idx >> 3, seg = (idx & 7) * 16;
            const size_t go = (size_t)row * ldbB + cb + seg;
            const uint32_t so = SWZ(row * 128 + seg);
            CP16(st + OFF_BH + so, gBh + go);
            CP16(st + OFF_BL + so, gBl + go);
        }
        CP_COMMIT();
    };

    float acc[4][8][4];
#pragma unroll
    for (int mi = 0; mi < 4; ++mi)
#pragma unroll
        for (int nf = 0; nf < 8; ++nf)
#pragma unroll
            for (int r = 0; r < 4; ++r) acc[mi][nf][r] = 0.f;

    const int lrow = lane & 15;
    const int lcb0 = (lane >> 4) * 16;
    const int arow = wm * 64 + lrow;
    const int brow = wn * 64 + lrow;

    load_chunk(0, 0);

    for (int c = 0; c < nkt; ++c) {
        const int buf = c & 1;
        if (c + 1 < nkt) { load_chunk(c + 1, buf ^ 1); CP_WAIT1(); }
        else             { CP_WAIT0(); }
        __syncthreads();

        const uint32_t st = sb + buf * STAGE;
#pragma unroll
        for (int kk = 0; kk < 4; ++kk) {
            const int cb = kk * 32 + lcb0;
            uint32_t ah[4][4], bh[4][4];
#pragma unroll
            for (int mi = 0; mi < 4; ++mi)
                ldsm4(ah[mi], st + OFF_AH + SWZ((arow + mi * 16) * 128 + cb));
#pragma unroll
            for (int nj = 0; nj < 4; ++nj)
                ldsm4(bh[nj], st + OFF_BH + SWZ((brow + nj * 16) * 128 + cb));
            // pass 1: Ah*Bh
#pragma unroll
            for (int mi = 0; mi < 4; ++mi)
#pragma unroll
                for (int nj = 0; nj < 4; ++nj) {
                    mma_bf16(acc[mi][nj * 2 + 0], ah[mi], bh[nj][0], bh[nj][2]);
                    mma_bf16(acc[mi][nj * 2 + 1], ah[mi], bh[nj][1], bh[nj][3]);
                }
            // pass 2: Al*Bh
            {
                uint32_t al[4][4];
#pragma unroll
                for (int mi = 0; mi < 4; ++mi)
                    ldsm4(al[mi], st + OFF_AL + SWZ((arow + mi * 16) * 128 + cb));
#pragma unroll
                for (int mi = 0; mi < 4; ++mi)
#pragma unroll
                    for (int nj = 0; nj < 4; ++nj) {
                        mma_bf16(acc[mi][nj * 2 + 0], al[mi], bh[nj][0], bh[nj][2]);
                        mma_bf16(acc[mi][nj * 2 + 1], al[mi], bh[nj][1], bh[nj][3]);
                    }
            }
            // pass 3: Ah*Bl
            {
                uint32_t bl[4][4];
#pragma unroll
                for (int nj = 0; nj < 4; ++nj)
                    ldsm4(bl[nj], st + OFF_BL + SWZ((brow + nj * 16) * 128 + cb));
#pragma unroll
                for (int mi = 0; mi < 4; ++mi)
#pragma unroll
                    for (int nj = 0; nj < 4; ++nj) {
                        mma_bf16(acc[mi][nj * 2 + 0], ah[mi], bl[nj][0], bl[nj][2]);
                        mma_bf16(acc[mi][nj * 2 + 1], ah[mi], bl[nj][1], bl[nj][3]);
                    }
            }
        }
        __syncthreads();
    }

    // ---- epilogue (register-direct) ----
    const int lr = lane >> 2;
    const int lc = (lane & 3) * 2;
#pragma unroll
    for (int mi = 0; mi < 4; ++mi) {
        const int row0 = bm * 128 + wm * 64 + mi * 16 + lr;
#pragma unroll
        for (int nf = 0; nf < 8; ++nf) {
            const int col = bn * 256 + wn * 64 + nf * 8 + lc;
            float* d = acc[mi][nf];
            if (MODE == 0) {
                const float b0 = bias[col], b1 = bias[col + 1];
                __nv_bfloat16 h0, l0, h1, l1;
                split_bf16(d[0] + b0, h0, l0); split_bf16(d[1] + b1, h1, l1);
                *(uint32_t*)(Chi + (size_t)row0 * ldc + col) = pack_bf2(h0, h1);
                *(uint32_t*)(Clo + (size_t)row0 * ldc + col) = pack_bf2(l0, l1);
                split_bf16(d[2] + b0, h0, l0); split_bf16(d[3] + b1, h1, l1);
                *(uint32_t*)(Chi + (size_t)(row0 + 8) * ldc + col) = pack_bf2(h0, h1);
                *(uint32_t*)(Clo + (size_t)(row0 + 8) * ldc + col) = pack_bf2(l0, l1);
            } else {
                float* cp = Cf + (size_t)bz * sC;
                float2 o0 = { d[0] * alpha, d[1] * alpha };
                float2 o1 = { d[2] * alpha, d[3] * alpha };
                *(float2*)(cp + (size_t)row0 * ldc + col) = o0;
                *(float2*)(cp + (size_t)(row0 + 8) * ldc + col) = o1;
            }
        }
    }
}

// ---------------------------------------------------------------------------
// Elementwise fp32 -> bf16 hi/lo split
// ---------------------------------------------------------------------------
__global__ void __launch_bounds__(256)
convert_split(const float* __restrict__ src, __nv_bfloat16* __restrict__ hi,
              __nv_bfloat16* __restrict__ lo, size_t n4)
{
    size_t i = (size_t)blockIdx.x * blockDim.x + threadIdx.x;
    if (i >= n4) return;
    float4 x = ((const float4*)src)[i];
    union { __nv_bfloat16 h[4]; uint2 u; } H, L;
    split_bf16(x.x, H.h[0], L.h[0]);
    split_bf16(x.y, H.h[1], L.h[1]);
    split_bf16(x.z, H.h[2], L.h[2]);
    split_bf16(x.w, H.h[3], L.h[3]);
    ((uint2*)hi)[i] = H.u;
    ((uint2*)lo)[i] = L.u;
}

// ---------------------------------------------------------------------------
// bf16 transpose per batch: src [B*S, H] -> dst [B][H][S]
// ---------------------------------------------------------------------------
__global__ void __launch_bounds__(256)
transpose_bf(const __nv_bfloat16* __restrict__ src, __nv_bfloat16* __restrict__ dst)
{
    __shared__ __nv_bfloat16 t[32][33];
    const int b = blockIdx.z;
    const int h0 = blockIdx.x * 32, s0 = blockIdx.y * 32;
    const int tx = threadIdx.x, ty = threadIdx.y;  // 32 x 8
#pragma unroll
    for (int i = 0; i < 4; ++i)
        t[ty + i * 8][tx] = src[((size_t)b * SS + s0 + ty + i * 8) * HD + h0 + tx];
    __syncthreads();
#pragma unroll
    for (int i = 0; i < 4; ++i)
        dst[((size_t)b * HD + h0 + ty + i * 8) * SS + s0 + tx] = t[tx][ty + i * 8];
}

// ---------------------------------------------------------------------------
// Masked causal softmax: SC fp32 -> P hi/lo bf16, zero-filled to 128-boundary.
// ---------------------------------------------------------------------------
__global__ void __launch_bounds__(256)
softmax_rows(const int* __restrict__ mask, const float* __restrict__ SC,
             __nv_bfloat16* __restrict__ Phi, __nv_bfloat16* __restrict__ Plo)
{
    const int b = blockIdx.y;
    const int i = blockIdx.x;
    const size_t rowoff = ((size_t)b * SS + i) * SS;
    const float* row = SC + rowoff;
    const int* mrow = mask + (size_t)b * SS;
    const int tid = threadIdx.x;
    const int nvalid = i + 1;
    const int nfill = ((i >> 7) + 1) << 7;

    float vals[8];
    float vmax = -INFINITY;
#pragma unroll
    for (int t = 0; t < 8; ++t) {
        int j = tid + t * 256;
        float s = -INFINITY;
        if (j < nvalid) {
            s = row[j];
            if (mrow[j] == 0) s = -1e9f;
        }
        vals[t] = s;
        vmax = fmaxf(vmax, s);
    }

    __shared__ float red[8];
#pragma unroll
    for (int o = 16; o; o >>= 1) vmax = fmaxf(vmax, __shfl_xor_sync(~0u, vmax, o));
    if ((tid & 31) == 0) red[tid >> 5] = vmax;
    __syncthreads();
    if (tid < 32) {
        float x = (tid < 8) ? red[tid] : -INFINITY;
#pragma unroll
        for (int o = 4; o; o >>= 1) x = fmaxf(x, __shfl_xor_sync(~0u, x, o));
        if (tid == 0) red[0] = x;
    }
    __syncthreads();
    vmax = red[0];
    __syncthreads();

    float lsum = 0.f;
#pragma unroll
    for (int t = 0; t < 8; ++t) {
        float e = __expf(vals[t] - vmax);
        vals[t] = e;
        lsum += e;
    }
#pragma unroll
    for (int o = 16; o; o >>= 1) lsum += __shfl_xor_sync(~0u, lsum, o);
    if ((tid & 31) == 0) red[tid >> 5] = lsum;
    __syncthreads();
    if (tid < 32) {
        float x = (tid < 8) ? red[tid] : 0.f;
#pragma unroll
        for (int o = 4; o; o >>= 1) x += __shfl_xor_sync(~0u, x, o);
        if (tid == 0) red[0] = x;
    }
    __syncthreads();
    const float rinv = 1.0f / red[0];

#pragma unroll
    for (int t = 0; t < 8; ++t) {
        int j = tid + t * 256;
        if (j < nfill) {
            float p = vals[t] * rinv;  // 0 for j > i
            __nv_bfloat16 H, L;
            split_bf16(p, H, L);
            Phi[rowoff + j] = H;
            Plo[rowoff + j] = L;
        }
    }
}

// ---------------------------------------------------------------------------
extern "C" void kernel_launch(void* const* d_in, const int* in_sizes, int n_in,
                              void* d_out, int out_size)
{
    (void)in_sizes; (void)n_in; (void)out_size;

    const float* q    = (const float*)d_in[0];
    const float* k    = (const float*)d_in[1];
    const float* v    = (const float*)d_in[2];
    const int*   mask = (const int*)  d_in[3];
    const float* Wq   = (const float*)d_in[4];
    const float* bq   = (const float*)d_in[5];
    const float* Wk   = (const float*)d_in[6];
    const float* bk   = (const float*)d_in[7];
    const float* Wv   = (const float*)d_in[8];
    const float* bv   = (const float*)d_in[9];
    float* out = (float*)d_out;

    static bool init = false;
    static __nv_bfloat16 *Xqh, *Xql, *Xkh, *Xkl, *Xvh, *Xvl;
    static __nv_bfloat16 *Wqh, *Wql, *Wkh, *Wkl, *Wvh, *Wvl;
    static __nv_bfloat16 *QHh, *QHl, *KHh, *KHl, *VHh, *VHl, *VTh, *VTl, *Ph, *Pl;
    static float *SC;
    if (!init) {
        void* p;
        cudaGetSymbolAddress(&p, g_Xq_hi); Xqh = (__nv_bfloat16*)p;
        cudaGetSymbolAddress(&p, g_Xq_lo); Xql = (__nv_bfloat16*)p;
        cudaGetSymbolAddress(&p, g_Xk_hi); Xkh = (__nv_bfloat16*)p;
        cudaGetSymbolAddress(&p, g_Xk_lo); Xkl = (__nv_bfloat16*)p;
        cudaGetSymbolAddress(&p, g_Xv_hi); Xvh = (__nv_bfloat16*)p;
        cudaGetSymbolAddress(&p, g_Xv_lo); Xvl = (__nv_bfloat16*)p;
        cudaGetSymbolAddress(&p, g_Wq_hi); Wqh = (__nv_bfloat16*)p;
        cudaGetSymbolAddress(&p, g_Wq_lo); Wql = (__nv_bfloat16*)p;
        cudaGetSymbolAddress(&p, g_Wk_hi); Wkh = (__nv_bfloat16*)p;
        cudaGetSymbolAddress(&p, g_Wk_lo); Wkl = (__nv_bfloat16*)p;
        cudaGetSymbolAddress(&p, g_Wv_hi); Wvh = (__nv_bfloat16*)p;
        cudaGetSymbolAddress(&p, g_Wv_lo); Wvl = (__nv_bfloat16*)p;
        cudaGetSymbolAddress(&p, g_QH_hi); QHh = (__nv_bfloat16*)p;
        cudaGetSymbolAddress(&p, g_QH_lo); QHl = (__nv_bfloat16*)p;
        cudaGetSymbolAddress(&p, g_KH_hi); KHh = (__nv_bfloat16*)p;
        cudaGetSymbolAddress(&p, g_KH_lo); KHl = (__nv_bfloat16*)p;
        cudaGetSymbolAddress(&p, g_VH_hi); VHh = (__nv_bfloat16*)p;
        cudaGetSymbolAddress(&p, g_VH_lo); VHl = (__nv_bfloat16*)p;
        cudaGetSymbolAddress(&p, g_VT_hi); VTh = (__nv_bfloat16*)p;
        cudaGetSymbolAddress(&p, g_VT_lo); VTl = (__nv_bfloat16*)p;
        cudaGetSymbolAddress(&p, g_P_hi);  Ph  = (__nv_bfloat16*)p;
        cudaGetSymbolAddress(&p, g_P_lo);  Pl  = (__nv_bfloat16*)p;
        cudaGetSymbolAddress(&p, g_SC);    SC  = (float*)p;
        cudaFuncSetAttribute((const void*)gemm3m<0>, cudaFuncAttributeMaxDynamicSharedMemorySize, SMEMSZ);
        cudaFuncSetAttribute((const void*)gemm3m<2>, cudaFuncAttributeMaxDynamicSharedMemorySize, SMEMSZ);
        cudaFuncSetAttribute((const void*)gemm3m<3>, cudaFuncAttributeMaxDynamicSharedMemorySize, SMEMSZ);
        init = true;
    }

    // 1) Split inputs to bf16 hi/lo
    const size_t nX4 = (size_t)NT * MD / 4;
    const size_t nW4 = (size_t)HD * MD / 4;
    convert_split<<<(unsigned)((nX4 + 255) / 256), 256>>>(q, Xqh, Xql, nX4);
    convert_split<<<(unsigned)((nX4 + 255) / 256), 256>>>(k, Xkh, Xkl, nX4);
    convert_split<<<(unsigned)((nX4 + 255) / 256), 256>>>(v, Xvh, Xvl, nX4);
    convert_split<<<(unsigned)((nW4 + 255) / 256), 256>>>(Wq, Wqh, Wql, nW4);
    convert_split<<<(unsigned)((nW4 + 255) / 256), 256>>>(Wk, Wkh, Wkl, nW4);
    convert_split<<<(unsigned)((nW4 + 255) / 256), 256>>>(Wv, Wvh, Wvl, nW4);

    // 2) Projections: [NT,1024] x [1024,1024]^T, CTA 128x256
    dim3 gproj(HD / 256, NT / 128, 1);
    gemm3m<0><<<gproj, 256, SMEMSZ>>>(Xqh, Xql, Wqh, Wql, bq, QHh, QHl, nullptr,
                                      MD, MD, HD, MD / KC, 1.f, 0, 0, 0);
    gemm3m<0><<<gproj, 256, SMEMSZ>>>(Xkh, Xkl, Wkh, Wkl, bk, KHh, KHl, nullptr,
                                      MD, MD, HD, MD / KC, 1.f, 0, 0, 0);
    gemm3m<0><<<gproj, 256, SMEMSZ>>>(Xvh, Xvl, Wvh, Wvl, bv, VHh, VHl, nullptr,
                                      MD, MD, HD, MD / KC, 1.f, 0, 0, 0);

    // 3) Transpose V to [B][H][S]
    dim3 gt(HD / 32, SS / 32, BB);
    transpose_bf<<<gt, dim3(32, 8)>>>(VHh, VTh);
    transpose_bf<<<gt, dim3(32, 8)>>>(VHl, VTl);

    // 4) Scores (causal tile skip), alpha = 1/sqrt(1024)
    dim3 gsc(SS / 256, SS / 128, BB);
    gemm3m<2><<<gsc, 256, SMEMSZ>>>(QHh, QHl, KHh, KHl, nullptr, nullptr, nullptr, SC,
                                    HD, HD, SS, HD / KC, 1.0f / 32.0f,
                                    (size_t)SS * HD, (size_t)SS * HD, (size_t)SS * SS);

    // 5) Softmax + bf16 hi/lo split of P
    softmax_rows<<<dim3(SS, BB), 256>>>(mask, SC, Ph, Pl);

    // 6) OUT = P @ VT^T (NT form; k-chunks limited by causality)
    dim3 go(HD / 256, SS / 128, BB);
    gemm3m<3><<<go, 256, SMEMSZ>>>(Ph, Pl, VTh, VTl, nullptr, nullptr, nullptr, out,
                                   SS, SS, HD, 0, 1.f,
                                   (size_t)SS * SS, (size_t)HD * SS, (size_t)SS * HD);
}

// round 5
// speedup vs baseline: 3.1674x; 1.3016x over previous
#include <cuda_runtime.h>
#include <cuda_fp16.h>
#include <math.h>
#include <stdint.h>

// Problem dims (fixed)
#define BB 4
#define SS 2048
#define MD 1024
#define HD 1024
#define NT 8192   // BB*SS

// GEMM tiling: CTA 128x256, 8 warps (2x4) of 64x64, K-chunk 64
#define KC 64
// 2-pass stage: A hi(16K) + A lo(16K) + B hi(32K)
#define OFF2_AH 0
#define OFF2_AL 16384
#define OFF2_BH 32768
#define STAGE2  65536
#define SMEM2   (3 * STAGE2)    // 192 KB, 3-stage
// 3-pass stage (scores): A hi/lo + B hi/lo
#define OFF3_AH 0
#define OFF3_AL 16384
#define OFF3_BH 32768
#define OFF3_BL 65536
#define STAGE3  98304
#define SMEM3   (2 * STAGE3)    // 192 KB, 2-stage

#define SWZ(o) ((o) ^ (((o) >> 3) & 0x70))

// ---------------------------------------------------------------------------
// Scratch (__device__ globals; allocation-free rule)
// ---------------------------------------------------------------------------
__device__ __align__(256) __half g_Xq_hi[(size_t)NT * MD];
__device__ __align__(256) __half g_Xq_lo[(size_t)NT * MD];
__device__ __align__(256) __half g_Xk_hi[(size_t)NT * MD];
__device__ __align__(256) __half g_Xk_lo[(size_t)NT * MD];
__device__ __align__(256) __half g_Xv_hi[(size_t)NT * MD];
__device__ __align__(256) __half g_Xv_lo[(size_t)NT * MD];
__device__ __align__(256) __half g_Wq_hi[(size_t)HD * MD];
__device__ __align__(256) __half g_Wk_hi[(size_t)HD * MD];
__device__ __align__(256) __half g_Wv_hi[(size_t)HD * MD];
__device__ __align__(256) __half g_QH_hi[(size_t)NT * HD];
__device__ __align__(256) __half g_QH_lo[(size_t)NT * HD];
__device__ __align__(256) __half g_KH_hi[(size_t)NT * HD];
__device__ __align__(256) __half g_KH_lo[(size_t)NT * HD];
__device__ __align__(256) __half g_VH_hi[(size_t)NT * HD];
__device__ __align__(256) __half g_VT_hi[(size_t)BB * HD * SS];
__device__ __align__(256) float  g_SC[(size_t)BB * SS * SS];
__device__ __align__(256) __half g_P_hi[(size_t)BB * SS * SS];
__device__ __align__(256) __half g_P_lo[(size_t)BB * SS * SS];

// ---------------------------------------------------------------------------
__device__ __forceinline__ uint32_t smem_u32(const void* p) {
    uint32_t a;
    asm("{ .reg .u64 t; cvta.to.shared.u64 t, %1; cvt.u32.u64 %0, t; }"
        : "=r"(a) : "l"(p));
    return a;
}
#define CP16(dst, src) asm volatile("cp.async.cg.shared.global [%0], [%1], 16;" :: "r"(dst), "l"(src))
#define CP_COMMIT()    asm volatile("cp.async.commit_group;" ::: "memory")
#define CP_WAIT1()     asm volatile("cp.async.wait_group 1;" ::: "memory")
#define CP_WAIT0()     asm volatile("cp.async.wait_group 0;" ::: "memory")

__device__ __forceinline__ void ldsm4(uint32_t r[4], uint32_t a) {
    asm volatile("ldmatrix.sync.aligned.m8n8.x4.shared.b16 {%0,%1,%2,%3}, [%4];"
                 : "=r"(r[0]), "=r"(r[1]), "=r"(r[2]), "=r"(r[3]) : "r"(a));
}
__device__ __forceinline__ void mma_f16(float d[4], const uint32_t a[4],
                                        uint32_t b0, uint32_t b1) {
    asm volatile(
        "mma.sync.aligned.m16n8k16.row.col.f32.f16.f16.f32 "
        "{%0,%1,%2,%3}, {%4,%5,%6,%7}, {%8,%9}, {%0,%1,%2,%3};"
        : "+f"(d[0]), "+f"(d[1]), "+f"(d[2]), "+f"(d[3])
        : "r"(a[0]), "r"(a[1]), "r"(a[2]), "r"(a[3]), "r"(b0), "r"(b1));
}

__device__ __forceinline__ void split_h(float x, __half& h, __half& l) {
    h = __float2half_rn(x);
    l = __float2half_rn(x - __half2float(h));
}
__device__ __forceinline__ uint32_t pack_h2(__half a, __half b) {
    union { __half2 v; uint32_t u; } t;
    t.v.x = a; t.v.y = b;
    return t.u;
}

// ---------------------------------------------------------------------------
// 2-pass fp16 mma.sync GEMM (NT): C = (Ah+Al)*Bh^T [+ bias]
// A: [M,K] hi/lo fp16 (lda). B: [N,K] hi fp16 (ldb).
// CTA 128x256, 8 warps of 64x64, KC=64, 3-stage cp.async, single sync/chunk.
// MODE 0: out fp16 hi/lo + bias (Q/K proj)
// MODE 1: out fp16 hi + bias (V proj)
// MODE 3: out fp32, k-chunks limited to (bm+1)*2 (PV)
// ---------------------------------------------------------------------------
template <int MODE>
__global__ void __launch_bounds__(256, 1)
gemm2p(const __half* __restrict__ Ahi, const __half* __restrict__ Alo,
       const __half* __restrict__ Bhi,
       const float* __restrict__ bias,
       __half* __restrict__ Chi, __half* __restrict__ Clo,
       float* __restrict__ Cf,
       int lda, int ldb, int ldc, int nkt0,
       size_t sA, size_t sB, size_t sC)
{
    const int bm = blockIdx.y, bn = blockIdx.x, bz = blockIdx.z;
    const int nkt = (MODE == 3) ? (bm + 1) * 2 : nkt0;

    extern __shared__ char smem[];
    const uint32_t sb = smem_u32(smem);
    const int tid = threadIdx.x, lane = tid & 31, wid = tid >> 5;
    const int wm = wid >> 2, wn = wid & 3;

    const char* gAh = (const char*)(Ahi + (size_t)bz * sA + (size_t)(bm * 128) * lda);
    const char* gAl = (const char*)(Alo + (size_t)bz * sA + (size_t)(bm * 128) * lda);
    const char* gBh = (const char*)(Bhi + (size_t)bz * sB + (size_t)(bn * 256) * ldb);
    const size_t ldaB = (size_t)lda * 2, ldbB = (size_t)ldb * 2;

    auto load_chunk = [&](int c, int buf) {
        const uint32_t st = sb + buf * STAGE2;
        const size_t cb = (size_t)c * 128;
#pragma unroll
        for (int i = 0; i < 4; ++i) {          // A: 128 rows x 128B (hi+lo)
            const int idx = tid + i * 256;
            const int row = idx >> 3, seg = (idx & 7) * 16;
            const size_t go = (size_t)row * ldaB + cb + seg;
            const uint32_t so = SWZ(row * 128 + seg);
            CP16(st + OFF2_AH + so, gAh + go);
            CP16(st + OFF2_AL + so, gAl + go);
        }
#pragma unroll
        for (int i = 0; i < 8; ++i) {          // B: 256 rows x 128B (hi)
            const int idx = tid + i * 256;
            const int row = idx >> 3, seg = (idx & 7) * 16;
            const size_t go = (size_t)row * ldbB + cb + seg;
            const uint32_t so = SWZ(row * 128 + seg);
            CP16(st + OFF2_BH + so, gBh + go);
        }
        CP_COMMIT();
    };

    float acc[4][8][4];
#pragma unroll
    for (int mi = 0; mi < 4; ++mi)
#pragma unroll
        for (int nf = 0; nf < 8; ++nf)
#pragma unroll
            for (int r = 0; r < 4; ++r) acc[mi][nf][r] = 0.f;

    const int lrow = lane & 15;
    const int lcb0 = (lane >> 4) * 16;
    const int arow = wm * 64 + lrow;
    const int brow = wn * 64 + lrow;

    load_chunk(0, 0);
    load_chunk(1, 1);

    for (int c = 0; c < nkt; ++c) {
        CP_WAIT1();
        __syncthreads();
        if (c + 2 < nkt) load_chunk(c + 2, (c + 2) % 3);
        else             CP_COMMIT();   // empty group keeps wait count aligned

        const uint32_t st = sb + (c % 3) * STAGE2;
#pragma unroll
        for (int kk = 0; kk < 4; ++kk) {
            const int cb = kk * 32 + lcb0;
            uint32_t ah[4][4], al[4][4], bh[4][4];
#pragma unroll
            for (int mi = 0; mi < 4; ++mi)
                ldsm4(ah[mi], st + OFF2_AH + SWZ((arow + mi * 16) * 128 + cb));
#pragma unroll
            for (int nj = 0; nj < 4; ++nj)
                ldsm4(bh[nj], st + OFF2_BH + SWZ((brow + nj * 16) * 128 + cb));
#pragma unroll
            for (int mi = 0; mi < 4; ++mi)
                ldsm4(al[mi], st + OFF2_AL + SWZ((arow + mi * 16) * 128 + cb));
#pragma unroll
            for (int mi = 0; mi < 4; ++mi)
#pragma unroll
                for (int nj = 0; nj < 4; ++nj) {
                    mma_f16(acc[mi][nj * 2 + 0], ah[mi], bh[nj][0], bh[nj][2]);
                    mma_f16(acc[mi][nj * 2 + 1], ah[mi], bh[nj][1], bh[nj][3]);
                }
#pragma unroll
            for (int mi = 0; mi < 4; ++mi)
#pragma unroll
                for (int nj = 0; nj < 4; ++nj) {
                    mma_f16(acc[mi][nj * 2 + 0], al[mi], bh[nj][0], bh[nj][2]);
                    mma_f16(acc[mi][nj * 2 + 1], al[mi], bh[nj][1], bh[nj][3]);
                }
        }
    }

    // ---- epilogue ----
    const int lr = lane >> 2;
    const int lc = (lane & 3) * 2;
#pragma unroll
    for (int mi = 0; mi < 4; ++mi) {
        const int row0 = bm * 128 + wm * 64 + mi * 16 + lr;
#pragma unroll
        for (int nf = 0; nf < 8; ++nf) {
            const int col = bn * 256 + wn * 64 + nf * 8 + lc;
            float* d = acc[mi][nf];
            if (MODE == 0) {
                const float b0 = bias[col], b1 = bias[col + 1];
                __half h0, l0, h1, l1;
                split_h(d[0] + b0, h0, l0); split_h(d[1] + b1, h1, l1);
                *(uint32_t*)(Chi + (size_t)row0 * ldc + col) = pack_h2(h0, h1);
                *(uint32_t*)(Clo + (size_t)row0 * ldc + col) = pack_h2(l0, l1);
                split_h(d[2] + b0, h0, l0); split_h(d[3] + b1, h1, l1);
                *(uint32_t*)(Chi + (size_t)(row0 + 8) * ldc + col) = pack_h2(h0, h1);
                *(uint32_t*)(Clo + (size_t)(row0 + 8) * ldc + col) = pack_h2(l0, l1);
            } else if (MODE == 1) {
                const float b0 = bias[col], b1 = bias[col + 1];
                *(uint32_t*)(Chi + (size_t)row0 * ldc + col) =
                    pack_h2(__float2half_rn(d[0] + b0), __float2half_rn(d[1] + b1));
                *(uint32_t*)(Chi + (size_t)(row0 + 8) * ldc + col) =
                    pack_h2(__float2half_rn(d[2] + b0), __float2half_rn(d[3] + b1));
            } else {
                float* cp = Cf + (size_t)bz * sC;
                float2 o0 = { d[0], d[1] };
                float2 o1 = { d[2], d[3] };
                *(float2*)(cp + (size_t)row0 * ldc + col) = o0;
                *(float2*)(cp + (size_t)(row0 + 8) * ldc + col) = o1;
            }
        }
    }
}

// ---------------------------------------------------------------------------
// 3-pass fp16 GEMM for scores (NT): C = alpha*((Ah+Al)*(Bh+Bl)^T - lo*lo)
// Causal tile skip; 2-stage pipeline (as validated in R4).
// ---------------------------------------------------------------------------
__global__ void __launch_bounds__(256, 1)
gemm3p_sc(const __half* __restrict__ Ahi, const __half* __restrict__ Alo,
          const __half* __restrict__ Bhi, const __half* __restrict__ Blo,
          float* __restrict__ Cf,
          int lda, int ldb, int ldc, int nkt, float alpha,
          size_t sA, size_t sB, size_t sC)
{
    const int bm = blockIdx.y, bn = blockIdx.x, bz = blockIdx.z;
    if (2 * bn > bm) return;

    extern __shared__ char smem[];
    const uint32_t sb = smem_u32(smem);
    const int tid = threadIdx.x, lane = tid & 31, wid = tid >> 5;
    const int wm = wid >> 2, wn = wid & 3;

    const char* gAh = (const char*)(Ahi + (size_t)bz * sA + (size_t)(bm * 128) * lda);
    const char* gAl = (const char*)(Alo + (size_t)bz * sA + (size_t)(bm * 128) * lda);
    const char* gBh = (const char*)(Bhi + (size_t)bz * sB + (size_t)(bn * 256) * ldb);
    const char* gBl = (const char*)(Blo + (size_t)bz * sB + (size_t)(bn * 256) * ldb);
    const size_t ldaB = (size_t)lda * 2, ldbB = (size_t)ldb * 2;

    auto load_chunk = [&](int c, int buf) {
        const uint32_t st = sb + buf * STAGE3;
        const size_t cb = (size_t)c * 128;
#pragma unroll
        for (int i = 0; i < 4; ++i) {
            const int idx = tid + i * 256;
            const int row = idx >> 3, seg = (idx & 7) * 16;
            const size_t go = (size_t)row * ldaB + cb + seg;
            const uint32_t so = SWZ(row * 128 + seg);
            CP16(st + OFF3_AH + so, gAh + go);
            CP16(st + OFF3_AL + so, gAl + go);
        }
#pragma unroll
        for (int i = 0; i < 8; ++i) {
            const int idx = tid + i * 256;
            const int row = idx >> 3, seg = (idx & 7) * 16;
            const size_t go = (size_t)row * ldbB + cb + seg;
            const uint32_t so = SWZ(row * 128 + seg);
            CP16(st + OFF3_BH + so, gBh + go);
            CP16(st + OFF3_BL + so, gBl + go);
        }
        CP_COMMIT();
    };

    float acc[4][8][4];
#pragma unroll
    for (int mi = 0; mi < 4; ++mi)
#pragma unroll
        for (int nf = 0; nf < 8; ++nf)
#pragma unroll
            for (int r = 0; r < 4; ++r) acc[mi][nf][r] = 0.f;

    const int lrow = lane & 15;
    const int lcb0 = (lane >> 4) * 16;
    const int arow = wm * 64 + lrow;
    const int brow = wn * 64 + lrow;

    load_chunk(0, 0);

    for (int c = 0; c < nkt; ++c) {
        const int buf = c & 1;
        if (c + 1 < nkt) { load_chunk(c + 1, buf ^ 1); CP_WAIT1(); }
        else             { CP_WAIT0(); }
        __syncthreads();

        const uint32_t st = sb + buf * STAGE3;
#pragma unroll
        for (int kk = 0; kk < 4; ++kk) {
            const int cb = kk * 32 + lcb0;
            uint32_t ah[4][4], bh[4][4];
#pragma unroll
            for (int mi = 0; mi < 4; ++mi)
                ldsm4(ah[mi], st + OFF3_AH + SWZ((arow + mi * 16) * 128 + cb));
#pragma unroll
            for (int nj = 0; nj < 4; ++nj)
                ldsm4(bh[nj], st + OFF3_BH + SWZ((brow + nj * 16) * 128 + cb));
#pragma unroll
            for (int mi = 0; mi < 4; ++mi)
#pragma unroll
                for (int nj = 0; nj < 4; ++nj) {
                    mma_f16(acc[mi][nj * 2 + 0], ah[mi], bh[nj][0], bh[nj][2]);
                    mma_f16(acc[mi][nj * 2 + 1], ah[mi], bh[nj][1], bh[nj][3]);
                }
            {
                uint32_t al[4][4];
#pragma unroll
                for (int mi = 0; mi < 4; ++mi)
                    ldsm4(al[mi], st + OFF3_AL + SWZ((arow + mi * 16) * 128 + cb));
#pragma unroll
                for (int mi = 0; mi < 4; ++mi)
#pragma unroll
                    for (int nj = 0; nj < 4; ++nj) {
                        mma_f16(acc[mi][nj * 2 + 0], al[mi], bh[nj][0], bh[nj][2]);
                        mma_f16(acc[mi][nj * 2 + 1], al[mi], bh[nj][1], bh[nj][3]);
                    }
            }
            {
                uint32_t bl[4][4];
#pragma unroll
                for (int nj = 0; nj < 4; ++nj)
                    ldsm4(bl[nj], st + OFF3_BL + SWZ((brow + nj * 16) * 128 + cb));
#pragma unroll
                for (int mi = 0; mi < 4; ++mi)
#pragma unroll
                    for (int nj = 0; nj < 4; ++nj) {
                        mma_f16(acc[mi][nj * 2 + 0], ah[mi], bl[nj][0], bl[nj][2]);
                        mma_f16(acc[mi][nj * 2 + 1], ah[mi], bl[nj][1], bl[nj][3]);
                    }
            }
        }
        __syncthreads();
    }

    const int lr = lane >> 2;
    const int lc = (lane & 3) * 2;
    float* cp = Cf + (size_t)bz * sC;
#pragma unroll
    for (int mi = 0; mi < 4; ++mi) {
        const int row0 = bm * 128 + wm * 64 + mi * 16 + lr;
#pragma unroll
        for (int nf = 0; nf < 8; ++nf) {
            const int col = bn * 256 + wn * 64 + nf * 8 + lc;
            float* d = acc[mi][nf];
            float2 o0 = { d[0] * alpha, d[1] * alpha };
            float2 o1 = { d[2] * alpha, d[3] * alpha };
            *(float2*)(cp + (size_t)row0 * ldc + col) = o0;
            *(float2*)(cp + (size_t)(row0 + 8) * ldc + col) = o1;
        }
    }
}

// ---------------------------------------------------------------------------
// fp32 -> fp16 hi/lo split (dual) and hi-only
// ---------------------------------------------------------------------------
__global__ void __launch_bounds__(256)
convert_split_h(const float* __restrict__ src, __half* __restrict__ hi,
                __half* __restrict__ lo, size_t n4)
{
    size_t i = (size_t)blockIdx.x * blockDim.x + threadIdx.x;
    if (i >= n4) return;
    float4 x = ((const float4*)src)[i];
    union { __half h[4]; uint2 u; } H, L;
    split_h(x.x, H.h[0], L.h[0]);
    split_h(x.y, H.h[1], L.h[1]);
    split_h(x.z, H.h[2], L.h[2]);
    split_h(x.w, H.h[3], L.h[3]);
    ((uint2*)hi)[i] = H.u;
    ((uint2*)lo)[i] = L.u;
}

__global__ void __launch_bounds__(256)
convert_hi(const float* __restrict__ src, __half* __restrict__ hi, size_t n4)
{
    size_t i = (size_t)blockIdx.x * blockDim.x + threadIdx.x;
    if (i >= n4) return;
    float4 x = ((const float4*)src)[i];
    union { __half h[4]; uint2 u; } H;
    H.h[0] = __float2half_rn(x.x);
    H.h[1] = __float2half_rn(x.y);
    H.h[2] = __float2half_rn(x.z);
    H.h[3] = __float2half_rn(x.w);
    ((uint2*)hi)[i] = H.u;
}

// ---------------------------------------------------------------------------
// fp16 transpose per batch: src [B*S, H] -> dst [B][H][S]
// ---------------------------------------------------------------------------
__global__ void __launch_bounds__(256)
transpose_h(const __half* __restrict__ src, __half* __restrict__ dst)
{
    __shared__ __half t[32][33];
    const int b = blockIdx.z;
    const int h0 = blockIdx.x * 32, s0 = blockIdx.y * 32;
    const int tx = threadIdx.x, ty = threadIdx.y;  // 32 x 8
#pragma unroll
    for (int i = 0; i < 4; ++i)
        t[ty + i * 8][tx] = src[((size_t)b * SS + s0 + ty + i * 8) * HD + h0 + tx];
    __syncthreads();
#pragma unroll
    for (int i = 0; i < 4; ++i)
        dst[((size_t)b * HD + h0 + ty + i * 8) * SS + s0 + tx] = t[tx][ty + i * 8];
}

// ---------------------------------------------------------------------------
// Masked causal softmax: SC fp32 -> P hi/lo fp16, zero-filled to 128-boundary.
// ---------------------------------------------------------------------------
__global__ void __launch_bounds__(256)
softmax_rows(const int* __restrict__ mask, const float* __restrict__ SC,
             __half* __restrict__ Phi, __half* __restrict__ Plo)
{
    const int b = blockIdx.y;
    const int i = blockIdx.x;
    const size_t rowoff = ((size_t)b * SS + i) * SS;
    const float* row = SC + rowoff;
    const int* mrow = mask + (size_t)b * SS;
    const int tid = threadIdx.x;
    const int nvalid = i + 1;
    const int nfill = ((i >> 7) + 1) << 7;

    float vals[8];
    float vmax = -INFINITY;
#pragma unroll
    for (int t = 0; t < 8; ++t) {
        int j = tid + t * 256;
        float s = -INFINITY;
        if (j < nvalid) {
            s = row[j];
            if (mrow[j] == 0) s = -1e9f;
        }
        vals[t] = s;
        vmax = fmaxf(vmax, s);
    }

    __shared__ float red[8];
#pragma unroll
    for (int o = 16; o; o >>= 1) vmax = fmaxf(vmax, __shfl_xor_sync(~0u, vmax, o));
    if ((tid & 31) == 0) red[tid >> 5] = vmax;
    __syncthreads();
    if (tid < 32) {
        float x = (tid < 8) ? red[tid] : -INFINITY;
#pragma unroll
        for (int o = 4; o; o >>= 1) x = fmaxf(x, __shfl_xor_sync(~0u, x, o));
        if (tid == 0) red[0] = x;
    }
    __syncthreads();
    vmax = red[0];
    __syncthreads();

    float lsum = 0.f;
#pragma unroll
    for (int t = 0; t < 8; ++t) {
        float e = __expf(vals[t] - vmax);
        vals[t] = e;
        lsum += e;
    }
#pragma unroll
    for (int o = 16; o; o >>= 1) lsum += __shfl_xor_sync(~0u, lsum, o);
    if ((tid & 31) == 0) red[tid >> 5] = lsum;
    __syncthreads();
    if (tid < 32) {
        float x = (tid < 8) ? red[tid] : 0.f;
#pragma unroll
        for (int o = 4; o; o >>= 1) x += __shfl_xor_sync(~0u, x, o);
        if (tid == 0) red[0] = x;
    }
    __syncthreads();
    const float rinv = 1.0f / red[0];

#pragma unroll
    for (int t = 0; t < 8; ++t) {
        int j = tid + t * 256;
        if (j < nfill) {
            float p = vals[t] * rinv;  // 0 for j > i
            __half H, L;
            split_h(p, H, L);
            Phi[rowoff + j] = H;
            Plo[rowoff + j] = L;
        }
    }
}

// ---------------------------------------------------------------------------
extern "C" void kernel_launch(void* const* d_in, const int* in_sizes, int n_in,
                              void* d_out, int out_size)
{
    (void)in_sizes; (void)n_in; (void)out_size;

    const float* q    = (const float*)d_in[0];
    const float* k    = (const float*)d_in[1];
    const float* v    = (const float*)d_in[2];
    const int*   mask = (const int*)  d_in[3];
    const float* Wq   = (const float*)d_in[4];
    const float* bq   = (const float*)d_in[5];
    const float* Wk   = (const float*)d_in[6];
    const float* bk   = (const float*)d_in[7];
    const float* Wv   = (const float*)d_in[8];
    const float* bv   = (const float*)d_in[9];
    float* out = (float*)d_out;

    static bool init = false;
    static __half *Xqh, *Xql, *Xkh, *Xkl, *Xvh, *Xvl;
    static __half *Wqh, *Wkh, *Wvh;
    static __half *QHh, *QHl, *KHh, *KHl, *VHh, *VTh, *Ph, *Pl;
    static float *SC;
    if (!init) {
        void* p;
        cudaGetSymbolAddress(&p, g_Xq_hi); Xqh = (__half*)p;
        cudaGetSymbolAddress(&p, g_Xq_lo); Xql = (__half*)p;
        cudaGetSymbolAddress(&p, g_Xk_hi); Xkh = (__half*)p;
        cudaGetSymbolAddress(&p, g_Xk_lo); Xkl = (__half*)p;
        cudaGetSymbolAddress(&p, g_Xv_hi); Xvh = (__half*)p;
        cudaGetSymbolAddress(&p, g_Xv_lo); Xvl = (__half*)p;
        cudaGetSymbolAddress(&p, g_Wq_hi); Wqh = (__half*)p;
        cudaGetSymbolAddress(&p, g_Wk_hi); Wkh = (__half*)p;
        cudaGetSymbolAddress(&p, g_Wv_hi); Wvh = (__half*)p;
        cudaGetSymbolAddress(&p, g_QH_hi); QHh = (__half*)p;
        cudaGetSymbolAddress(&p, g_QH_lo); QHl = (__half*)p;
        cudaGetSymbolAddress(&p, g_KH_hi); KHh = (__half*)p;
        cudaGetSymbolAddress(&p, g_KH_lo); KHl = (__half*)p;
        cudaGetSymbolAddress(&p, g_VH_hi); VHh = (__half*)p;
        cudaGetSymbolAddress(&p, g_VT_hi); VTh = (__half*)p;
        cudaGetSymbolAddress(&p, g_P_hi);  Ph  = (__half*)p;
        cudaGetSymbolAddress(&p, g_P_lo);  Pl  = (__half*)p;
        cudaGetSymbolAddress(&p, g_SC);    SC  = (float*)p;
        cudaFuncSetAttribute((const void*)gemm2p<0>, cudaFuncAttributeMaxDynamicSharedMemorySize, SMEM2);
        cudaFuncSetAttribute((const void*)gemm2p<1>, cudaFuncAttributeMaxDynamicSharedMemorySize, SMEM2);
        cudaFuncSetAttribute((const void*)gemm2p<3>, cudaFuncAttributeMaxDynamicSharedMemorySize, SMEM2);
        cudaFuncSetAttribute((const void*)gemm3p_sc, cudaFuncAttributeMaxDynamicSharedMemorySize, SMEM3);
        init = true;
    }

    // 1) Convert inputs: X dual fp16, W hi only
    const size_t nX4 = (size_t)NT * MD / 4;
    const size_t nW4 = (size_t)HD * MD / 4;
    convert_split_h<<<(unsigned)((nX4 + 255) / 256), 256>>>(q, Xqh, Xql, nX4);
    convert_split_h<<<(unsigned)((nX4 + 255) / 256), 256>>>(k, Xkh, Xkl, nX4);
    convert_split_h<<<(unsigned)((nX4 + 255) / 256), 256>>>(v, Xvh, Xvl, nX4);
    convert_hi<<<(unsigned)((nW4 + 255) / 256), 256>>>(Wq, Wqh, nW4);
    convert_hi<<<(unsigned)((nW4 + 255) / 256), 256>>>(Wk, Wkh, nW4);
    convert_hi<<<(unsigned)((nW4 + 255) / 256), 256>>>(Wv, Wvh, nW4);

    // 2) Projections (2-pass): Q/K -> dual out, V -> single out
    dim3 gproj(HD / 256, NT / 128, 1);
    gemm2p<0><<<gproj, 256, SMEM2>>>(Xqh, Xql, Wqh, bq, QHh, QHl, nullptr,
                                     MD, MD, HD, MD / KC, 0, 0, 0);
    gemm2p<0><<<gproj, 256, SMEM2>>>(Xkh, Xkl, Wkh, bk, KHh, KHl, nullptr,
                                     MD, MD, HD, MD / KC, 0, 0, 0);
    gemm2p<1><<<gproj, 256, SMEM2>>>(Xvh, Xvl, Wvh, bv, VHh, nullptr, nullptr,
                                     MD, MD, HD, MD / KC, 0, 0, 0);

    // 3) Transpose V (hi) to [B][H][S]
    dim3 gt(HD / 32, SS / 32, BB);
    transpose_h<<<gt, dim3(32, 8)>>>(VHh, VTh);

    // 4) Scores (3-pass, causal skip), alpha = 1/sqrt(1024)
    dim3 gsc(SS / 256, SS / 128, BB);
    gemm3p_sc<<<gsc, 256, SMEM3>>>(QHh, QHl, KHh, KHl, SC,
                                   HD, HD, SS, HD / KC, 1.0f / 32.0f,
                                   (size_t)SS * HD, (size_t)SS * HD, (size_t)SS * SS);

    // 5) Softmax + fp16 hi/lo split of P
    softmax_rows<<<dim3(SS, BB), 256>>>(mask, SC, Ph, Pl);

    // 6) OUT = P @ VT^T (2-pass NT; k-chunks limited by causality)
    dim3 go(HD / 256, SS / 128, BB);
    gemm2p<3><<<go, 256, SMEM2>>>(Ph, Pl, VTh, nullptr, nullptr, nullptr, out,
                                  SS, SS, HD, 0,
                                  (size_t)SS * SS, (size_t)HD * SS, (size_t)SS * HD);
}

// round 6
// speedup vs baseline: 3.2403x; 1.0230x over previous
#include <cuda_runtime.h>
#include <cuda_fp16.h>
#include <math.h>
#include <stdint.h>

// Problem dims (fixed)
#define BB 4
#define SS 2048
#define MD 1024
#define HD 1024
#define NT 8192   // BB*SS

// GEMM tiling: CTA 128x256, 16 warps (2x8) of 64x32, K-chunk 64
#define KC 64
// Stage: A hi(16K) + A lo(16K) + B hi(32K) = 64KB, 3 stages
#define OFF_AH 0
#define OFF_AL 16384
#define OFF_BH 32768
#define STAGE  65536
#define SMEMSZ (3 * STAGE)    // 192 KB

#define SWZ(o) ((o) ^ (((o) >> 3) & 0x70))

// ---------------------------------------------------------------------------
// Scratch (__device__ globals; allocation-free rule)
// ---------------------------------------------------------------------------
__device__ __align__(256) __half g_Xq_hi[(size_t)NT * MD];
__device__ __align__(256) __half g_Xq_lo[(size_t)NT * MD];
__device__ __align__(256) __half g_Xk_hi[(size_t)NT * MD];
__device__ __align__(256) __half g_Xk_lo[(size_t)NT * MD];
__device__ __align__(256) __half g_Xv_hi[(size_t)NT * MD];
__device__ __align__(256) __half g_Xv_lo[(size_t)NT * MD];
__device__ __align__(256) __half g_Wq_hi[(size_t)HD * MD];
__device__ __align__(256) __half g_Wk_hi[(size_t)HD * MD];
__device__ __align__(256) __half g_Wv_hi[(size_t)HD * MD];
__device__ __align__(256) __half g_QH_hi[(size_t)NT * HD];
__device__ __align__(256) __half g_QH_lo[(size_t)NT * HD];
__device__ __align__(256) __half g_KH_hi[(size_t)NT * HD];
__device__ __align__(256) __half g_VH_hi[(size_t)NT * HD];
__device__ __align__(256) __half g_VT_hi[(size_t)BB * HD * SS];
__device__ __align__(256) float  g_SC[(size_t)BB * SS * SS];
__device__ __align__(256) __half g_P_hi[(size_t)BB * SS * SS];
__device__ __align__(256) __half g_P_lo[(size_t)BB * SS * SS];

// ---------------------------------------------------------------------------
__device__ __forceinline__ uint32_t smem_u32(const void* p) {
    uint32_t a;
    asm("{ .reg .u64 t; cvta.to.shared.u64 t, %1; cvt.u32.u64 %0, t; }"
        : "=r"(a) : "l"(p));
    return a;
}
#define CP16(dst, src) asm volatile("cp.async.cg.shared.global [%0], [%1], 16;" :: "r"(dst), "l"(src))
#define CP_COMMIT()    asm volatile("cp.async.commit_group;" ::: "memory")
#define CP_WAIT1()     asm volatile("cp.async.wait_group 1;" ::: "memory")

__device__ __forceinline__ void ldsm4(uint32_t r[4], uint32_t a) {
    asm volatile("ldmatrix.sync.aligned.m8n8.x4.shared.b16 {%0,%1,%2,%3}, [%4];"
                 : "=r"(r[0]), "=r"(r[1]), "=r"(r[2]), "=r"(r[3]) : "r"(a));
}
__device__ __forceinline__ void mma_f16(float d[4], const uint32_t a[4],
                                        uint32_t b0, uint32_t b1) {
    asm volatile(
        "mma.sync.aligned.m16n8k16.row.col.f32.f16.f16.f32 "
        "{%0,%1,%2,%3}, {%4,%5,%6,%7}, {%8,%9}, {%0,%1,%2,%3};"
        : "+f"(d[0]), "+f"(d[1]), "+f"(d[2]), "+f"(d[3])
        : "r"(a[0]), "r"(a[1]), "r"(a[2]), "r"(a[3]), "r"(b0), "r"(b1));
}

__device__ __forceinline__ void split_h(float x, __half& h, __half& l) {
    h = __float2half_rn(x);
    l = __float2half_rn(x - __half2float(h));
}
__device__ __forceinline__ uint32_t pack_h2(__half a, __half b) {
    union { __half2 v; uint32_t u; } t;
    t.v.x = a; t.v.y = b;
    return t.u;
}

// ---------------------------------------------------------------------------
// Unified 2-pass fp16 mma.sync GEMM (NT): C = (Ah+Al)*Bh^T [+ bias] [*alpha]
// A: [M,K] hi/lo fp16 (lda). B: [N,K] hi fp16 (ldb).
// CTA 128x256, 16 warps (2x8) of 64x32, KC=64, 3-stage cp.async, 1 sync/chunk.
// MODE 0: out fp16 hi/lo + bias (Q proj)
// MODE 1: out fp16 hi + bias (K/V proj)
// MODE 2: out fp32 * alpha, causal tile skip 2*bn>bm (scores)
// MODE 3: out fp32, k-chunks limited to (bm+1)*2 (PV)
// ---------------------------------------------------------------------------
template <int MODE>
__global__ void __launch_bounds__(512, 1)
gemm2p(const __half* __restrict__ Ahi, const __half* __restrict__ Alo,
       const __half* __restrict__ Bhi,
       const float* __restrict__ bias,
       __half* __restrict__ Chi, __half* __restrict__ Clo,
       float* __restrict__ Cf,
       int lda, int ldb, int ldc, int nkt0, float alpha,
       size_t sA, size_t sB, size_t sC)
{
    const int bm = blockIdx.y, bn = blockIdx.x, bz = blockIdx.z;
    if (MODE == 2 && 2 * bn > bm) return;
    const int nkt = (MODE == 3) ? (bm + 1) * 2 : nkt0;

    extern __shared__ char smem[];
    const uint32_t sb = smem_u32(smem);
    const int tid = threadIdx.x, lane = tid & 31, wid = tid >> 5;
    const int wm = wid >> 3, wn = wid & 7;

    const char* gAh = (const char*)(Ahi + (size_t)bz * sA + (size_t)(bm * 128) * lda);
    const char* gAl = (const char*)(Alo + (size_t)bz * sA + (size_t)(bm * 128) * lda);
    const char* gBh = (const char*)(Bhi + (size_t)bz * sB + (size_t)(bn * 256) * ldb);
    const size_t ldaB = (size_t)lda * 2, ldbB = (size_t)ldb * 2;

    auto load_chunk = [&](int c, int buf) {
        const uint32_t st = sb + buf * STAGE;
        const size_t cb = (size_t)c * 128;
#pragma unroll
        for (int i = 0; i < 2; ++i) {          // A: 128 rows x 128B (hi+lo)
            const int idx = tid + i * 512;
            const int row = idx >> 3, seg = (idx & 7) * 16;
            const size_t go = (size_t)row * ldaB + cb + seg;
            const uint32_t so = SWZ(row * 128 + seg);
            CP16(st + OFF_AH + so, gAh + go);
            CP16(st + OFF_AL + so, gAl + go);
        }
#pragma unroll
        for (int i = 0; i < 4; ++i) {          // B: 256 rows x 128B (hi)
            const int idx = tid + i * 512;
            const int row = idx >> 3, seg = (idx & 7) * 16;
            const size_t go = (size_t)row * ldbB + cb + seg;
            const uint32_t so = SWZ(row * 128 + seg);
            CP16(st + OFF_BH + so, gBh + go);
        }
        CP_COMMIT();
    };

    float acc[4][4][4];
#pragma unroll
    for (int mi = 0; mi < 4; ++mi)
#pragma unroll
        for (int nf = 0; nf < 4; ++nf)
#pragma unroll
            for (int r = 0; r < 4; ++r) acc[mi][nf][r] = 0.f;

    const int lrow = lane & 15;
    const int lcb0 = (lane >> 4) * 16;
    const int arow = wm * 64 + lrow;
    const int brow = wn * 32 + lrow;

    load_chunk(0, 0);
    load_chunk(1, 1);

    for (int c = 0; c < nkt; ++c) {
        CP_WAIT1();
        __syncthreads();
        if (c + 2 < nkt) load_chunk(c + 2, (c + 2) % 3);
        else             CP_COMMIT();   // empty group keeps wait count aligned

        const uint32_t st = sb + (c % 3) * STAGE;
#pragma unroll
        for (int kk = 0; kk < 4; ++kk) {
            const int cb = kk * 32 + lcb0;
            uint32_t a[4][4], bh[2][4];
#pragma unroll
            for (int mi = 0; mi < 4; ++mi)
                ldsm4(a[mi], st + OFF_AH + SWZ((arow + mi * 16) * 128 + cb));
#pragma unroll
            for (int nj = 0; nj < 2; ++nj)
                ldsm4(bh[nj], st + OFF_BH + SWZ((brow + nj * 16) * 128 + cb));
#pragma unroll
            for (int mi = 0; mi < 4; ++mi)
#pragma unroll
                for (int nj = 0; nj < 2; ++nj) {
                    mma_f16(acc[mi][nj * 2 + 0], a[mi], bh[nj][0], bh[nj][2]);
                    mma_f16(acc[mi][nj * 2 + 1], a[mi], bh[nj][1], bh[nj][3]);
                }
            // reload A regs with lo parts (WAR handled by scoreboard)
#pragma unroll
            for (int mi = 0; mi < 4; ++mi)
                ldsm4(a[mi], st + OFF_AL + SWZ((arow + mi * 16) * 128 + cb));
#pragma unroll
            for (int mi = 0; mi < 4; ++mi)
#pragma unroll
                for (int nj = 0; nj < 2; ++nj) {
                    mma_f16(acc[mi][nj * 2 + 0], a[mi], bh[nj][0], bh[nj][2]);
                    mma_f16(acc[mi][nj * 2 + 1], a[mi], bh[nj][1], bh[nj][3]);
                }
        }
    }

    // ---- epilogue ----
    const int lr = lane >> 2;
    const int lc = (lane & 3) * 2;
#pragma unroll
    for (int mi = 0; mi < 4; ++mi) {
        const int row0 = bm * 128 + wm * 64 + mi * 16 + lr;
#pragma unroll
        for (int nf = 0; nf < 4; ++nf) {
            const int col = bn * 256 + wn * 32 + nf * 8 + lc;
            float* d = acc[mi][nf];
            if (MODE == 0) {
                const float b0 = bias[col], b1 = bias[col + 1];
                __half h0, l0, h1, l1;
                split_h(d[0] + b0, h0, l0); split_h(d[1] + b1, h1, l1);
                *(uint32_t*)(Chi + (size_t)row0 * ldc + col) = pack_h2(h0, h1);
                *(uint32_t*)(Clo + (size_t)row0 * ldc + col) = pack_h2(l0, l1);
                split_h(d[2] + b0, h0, l0); split_h(d[3] + b1, h1, l1);
                *(uint32_t*)(Chi + (size_t)(row0 + 8) * ldc + col) = pack_h2(h0, h1);
                *(uint32_t*)(Clo + (size_t)(row0 + 8) * ldc + col) = pack_h2(l0, l1);
            } else if (MODE == 1) {
                const float b0 = bias[col], b1 = bias[col + 1];
                *(uint32_t*)(Chi + (size_t)row0 * ldc + col) =
                    pack_h2(__float2half_rn(d[0] + b0), __float2half_rn(d[1] + b1));
                *(uint32_t*)(Chi + (size_t)(row0 + 8) * ldc + col) =
                    pack_h2(__float2half_rn(d[2] + b0), __float2half_rn(d[3] + b1));
            } else {
                float* cp = Cf + (size_t)bz * sC;
                float2 o0 = { d[0] * alpha, d[1] * alpha };
                float2 o1 = { d[2] * alpha, d[3] * alpha };
                *(float2*)(cp + (size_t)row0 * ldc + col) = o0;
                *(float2*)(cp + (size_t)(row0 + 8) * ldc + col) = o1;
            }
        }
    }
}

// ---------------------------------------------------------------------------
// fp32 -> fp16 hi/lo split (dual) and hi-only
// ---------------------------------------------------------------------------
__global__ void __launch_bounds__(256)
convert_split_h(const float* __restrict__ src, __half* __restrict__ hi,
                __half* __restrict__ lo, size_t n4)
{
    size_t i = (size_t)blockIdx.x * blockDim.x + threadIdx.x;
    if (i >= n4) return;
    float4 x = ((const float4*)src)[i];
    union { __half h[4]; uint2 u; } H, L;
    split_h(x.x, H.h[0], L.h[0]);
    split_h(x.y, H.h[1], L.h[1]);
    split_h(x.z, H.h[2], L.h[2]);
    split_h(x.w, H.h[3], L.h[3]);
    ((uint2*)hi)[i] = H.u;
    ((uint2*)lo)[i] = L.u;
}

__global__ void __launch_bounds__(256)
convert_hi(const float* __restrict__ src, __half* __restrict__ hi, size_t n4)
{
    size_t i = (size_t)blockIdx.x * blockDim.x + threadIdx.x;
    if (i >= n4) return;
    float4 x = ((const float4*)src)[i];
    union { __half h[4]; uint2 u; } H;
    H.h[0] = __float2half_rn(x.x);
    H.h[1] = __float2half_rn(x.y);
    H.h[2] = __float2half_rn(x.z);
    H.h[3] = __float2half_rn(x.w);
    ((uint2*)hi)[i] = H.u;
}

// ---------------------------------------------------------------------------
// fp16 transpose per batch: src [B*S, H] -> dst [B][H][S]
// ---------------------------------------------------------------------------
__global__ void __launch_bounds__(256)
transpose_h(const __half* __restrict__ src, __half* __restrict__ dst)
{
    __shared__ __half t[32][33];
    const int b = blockIdx.z;
    const int h0 = blockIdx.x * 32, s0 = blockIdx.y * 32;
    const int tx = threadIdx.x, ty = threadIdx.y;  // 32 x 8
#pragma unroll
    for (int i = 0; i < 4; ++i)
        t[ty + i * 8][tx] = src[((size_t)b * SS + s0 + ty + i * 8) * HD + h0 + tx];
    __syncthreads();
#pragma unroll
    for (int i = 0; i < 4; ++i)
        dst[((size_t)b * HD + h0 + ty + i * 8) * SS + s0 + tx] = t[tx][ty + i * 8];
}

// ---------------------------------------------------------------------------
// Masked causal softmax: SC fp32 -> P hi/lo fp16, zero-filled to 128-boundary.
// ---------------------------------------------------------------------------
__global__ void __launch_bounds__(256)
softmax_rows(const int* __restrict__ mask, const float* __restrict__ SC,
             __half* __restrict__ Phi, __half* __restrict__ Plo)
{
    const int b = blockIdx.y;
    const int i = blockIdx.x;
    const size_t rowoff = ((size_t)b * SS + i) * SS;
    const float* row = SC + rowoff;
    const int* mrow = mask + (size_t)b * SS;
    const int tid = threadIdx.x;
    const int nvalid = i + 1;
    const int nfill = ((i >> 7) + 1) << 7;

    float vals[8];
    float vmax = -INFINITY;
#pragma unroll
    for (int t = 0; t < 8; ++t) {
        int j = tid + t * 256;
        float s = -INFINITY;
        if (j < nvalid) {
            s = row[j];
            if (mrow[j] == 0) s = -1e9f;
        }
        vals[t] = s;
        vmax = fmaxf(vmax, s);
    }

    __shared__ float red[8];
#pragma unroll
    for (int o = 16; o; o >>= 1) vmax = fmaxf(vmax, __shfl_xor_sync(~0u, vmax, o));
    if ((tid & 31) == 0) red[tid >> 5] = vmax;
    __syncthreads();
    if (tid < 32) {
        float x = (tid < 8) ? red[tid] : -INFINITY;
#pragma unroll
        for (int o = 4; o; o >>= 1) x = fmaxf(x, __shfl_xor_sync(~0u, x, o));
        if (tid == 0) red[0] = x;
    }
    __syncthreads();
    vmax = red[0];
    __syncthreads();

    float lsum = 0.f;
#pragma unroll
    for (int t = 0; t < 8; ++t) {
        float e = __expf(vals[t] - vmax);
        vals[t] = e;
        lsum += e;
    }
#pragma unroll
    for (int o = 16; o; o >>= 1) lsum += __shfl_xor_sync(~0u, lsum, o);
    if ((tid & 31) == 0) red[tid >> 5] = lsum;
    __syncthreads();
    if (tid < 32) {
        float x = (tid < 8) ? red[tid] : 0.f;
#pragma unroll
        for (int o = 4; o; o >>= 1) x += __shfl_xor_sync(~0u, x, o);
        if (tid == 0) red[0] = x;
    }
    __syncthreads();
    const float rinv = 1.0f / red[0];

#pragma unroll
    for (int t = 0; t < 8; ++t) {
        int j = tid + t * 256;
        if (j < nfill) {
            float p = vals[t] * rinv;  // 0 for j > i
            __half H, L;
            split_h(p, H, L);
            Phi[rowoff + j] = H;
            Plo[rowoff + j] = L;
        }
    }
}

// ---------------------------------------------------------------------------
extern "C" void kernel_launch(void* const* d_in, const int* in_sizes, int n_in,
                              void* d_out, int out_size)
{
    (void)in_sizes; (void)n_in; (void)out_size;

    const float* q    = (const float*)d_in[0];
    const float* k    = (const float*)d_in[1];
    const float* v    = (const float*)d_in[2];
    const int*   mask = (const int*)  d_in[3];
    const float* Wq   = (const float*)d_in[4];
    const float* bq   = (const float*)d_in[5];
    const float* Wk   = (const float*)d_in[6];
    const float* bk   = (const float*)d_in[7];
    const float* Wv   = (const float*)d_in[8];
    const float* bv   = (const float*)d_in[9];
    float* out = (float*)d_out;

    static bool init = false;
    static __half *Xqh, *Xql, *Xkh, *Xkl, *Xvh, *Xvl;
    static __half *Wqh, *Wkh, *Wvh;
    static __half *QHh, *QHl, *KHh, *VHh, *VTh, *Ph, *Pl;
    static float *SC;
    if (!init) {
        void* p;
        cudaGetSymbolAddress(&p, g_Xq_hi); Xqh = (__half*)p;
        cudaGetSymbolAddress(&p, g_Xq_lo); Xql = (__half*)p;
        cudaGetSymbolAddress(&p, g_Xk_hi); Xkh = (__half*)p;
        cudaGetSymbolAddress(&p, g_Xk_lo); Xkl = (__half*)p;
        cudaGetSymbolAddress(&p, g_Xv_hi); Xvh = (__half*)p;
        cudaGetSymbolAddress(&p, g_Xv_lo); Xvl = (__half*)p;
        cudaGetSymbolAddress(&p, g_Wq_hi); Wqh = (__half*)p;
        cudaGetSymbolAddress(&p, g_Wk_hi); Wkh = (__half*)p;
        cudaGetSymbolAddress(&p, g_Wv_hi); Wvh = (__half*)p;
        cudaGetSymbolAddress(&p, g_QH_hi); QHh = (__half*)p;
        cudaGetSymbolAddress(&p, g_QH_lo); QHl = (__half*)p;
        cudaGetSymbolAddress(&p, g_KH_hi); KHh = (__half*)p;
        cudaGetSymbolAddress(&p, g_VH_hi); VHh = (__half*)p;
        cudaGetSymbolAddress(&p, g_VT_hi); VTh = (__half*)p;
        cudaGetSymbolAddress(&p, g_P_hi);  Ph  = (__half*)p;
        cudaGetSymbolAddress(&p, g_P_lo);  Pl  = (__half*)p;
        cudaGetSymbolAddress(&p, g_SC);    SC  = (float*)p;
        cudaFuncSetAttribute((const void*)gemm2p<0>, cudaFuncAttributeMaxDynamicSharedMemorySize, SMEMSZ);
        cudaFuncSetAttribute((const void*)gemm2p<1>, cudaFuncAttributeMaxDynamicSharedMemorySize, SMEMSZ);
        cudaFuncSetAttribute((const void*)gemm2p<2>, cudaFuncAttributeMaxDynamicSharedMemorySize, SMEMSZ);
        cudaFuncSetAttribute((const void*)gemm2p<3>, cudaFuncAttributeMaxDynamicSharedMemorySize, SMEMSZ);
        init = true;
    }

    // 1) Convert inputs: X dual fp16, W hi only
    const size_t nX4 = (size_t)NT * MD / 4;
    const size_t nW4 = (size_t)HD * MD / 4;
    convert_split_h<<<(unsigned)((nX4 + 255) / 256), 256>>>(q, Xqh, Xql, nX4);
    convert_split_h<<<(unsigned)((nX4 + 255) / 256), 256>>>(k, Xkh, Xkl, nX4);
    convert_split_h<<<(unsigned)((nX4 + 255) / 256), 256>>>(v, Xvh, Xvl, nX4);
    convert_hi<<<(unsigned)((nW4 + 255) / 256), 256>>>(Wq, Wqh, nW4);
    convert_hi<<<(unsigned)((nW4 + 255) / 256), 256>>>(Wk, Wkh, nW4);
    convert_hi<<<(unsigned)((nW4 + 255) / 256), 256>>>(Wv, Wvh, nW4);

    // 2) Projections: Q -> dual out, K/V -> hi out
    dim3 gproj(HD / 256, NT / 128, 1);
    gemm2p<0><<<gproj, 512, SMEMSZ>>>(Xqh, Xql, Wqh, bq, QHh, QHl, nullptr,
                                      MD, MD, HD, MD / KC, 1.f, 0, 0, 0);
    gemm2p<1><<<gproj, 512, SMEMSZ>>>(Xkh, Xkl, Wkh, bk, KHh, nullptr, nullptr,
                                      MD, MD, HD, MD / KC, 1.f, 0, 0, 0);
    gemm2p<1><<<gproj, 512, SMEMSZ>>>(Xvh, Xvl, Wvh, bv, VHh, nullptr, nullptr,
                                      MD, MD, HD, MD / KC, 1.f, 0, 0, 0);

    // 3) Transpose V (hi) to [B][H][S]
    dim3 gt(HD / 32, SS / 32, BB);
    transpose_h<<<gt, dim3(32, 8)>>>(VHh, VTh);

    // 4) Scores (2-pass, causal skip), alpha = 1/sqrt(1024)
    dim3 gsc(SS / 256, SS / 128, BB);
    gemm2p<2><<<gsc, 512, SMEMSZ>>>(QHh, QHl, KHh, nullptr, nullptr, nullptr, SC,
                                    HD, HD, SS, HD / KC, 1.0f / 32.0f,
                                    (size_t)SS * HD, (size_t)SS * HD, (size_t)SS * SS);

    // 5) Softmax + fp16 hi/lo split of P
    softmax_rows<<<dim3(SS, BB), 256>>>(mask, SC, Ph, Pl);

    // 6) OUT = P @ VT^T (2-pass NT; k-chunks limited by causality)
    dim3 go(HD / 256, SS / 128, BB);
    gemm2p<3><<<go, 512, SMEMSZ>>>(Ph, Pl, VTh, nullptr, nullptr, nullptr, out,
                                   SS, SS, HD, 0, 1.f,
                                   (size_t)SS * SS, (size_t)HD * SS, (size_t)SS * HD);
}